// round 7
// baseline (speedup 1.0000x reference)
#include <cuda_runtime.h>
#include <math.h>

#define NN     32
#define TIN    12
#define HID    64
#define HEADS  8
#define HH     512
#define EPB    256
#define ET     288
#define E_     131072
#define NTH    256
#define RS     68
#define H2S    68
#define HLNTS  36
#define XIS    196
#define YSS    68

#define O_H1    0
#define O_XI    0
#define O_YS    12544
#define O_X     17408
#define O_ES2   17408
#define O_ED2   17440
#define O_M2    17472
#define O_IS2   17504
#define O_AL2   17536
#define O_ES    17792
#define O_E2    17824
#define O_ED    18048
#define O_E     18304
#define O_HLNT  18304
#define O_SRC   20608
#define O_DST   20896
#define O_CNT   21184
#define O_OFF   21216
#define O_SLOT  21249
#define O_CSR   21537
#define O_H2    21828
#define O_G2    24004
#define O_HSM   24004
#define O_GH    24068
#define SMEM_FLOATS 26180

typedef unsigned long long u64t;

#define BAR_SYNC(id, n)   asm volatile("bar.sync %0, %1;"   :: "n"(id), "n"(n) : "memory")
#define BAR_ARRIVE(id, n) asm volatile("bar.arrive %0, %1;" :: "n"(id), "n"(n) : "memory")

__device__ __forceinline__ u64t pk2(float lo, float hi) {
    u64t r; asm("mov.b64 %0, {%1, %2};" : "=l"(r) : "f"(lo), "f"(hi)); return r;
}
__device__ __forceinline__ void fma2(u64t& d, u64t a, u64t b) {
    asm("fma.rn.f32x2 %0, %1, %2, %3;" : "=l"(d) : "l"(a), "l"(b), "l"(d));
}
__device__ __forceinline__ float2 up2(u64t v) {
    float2 f; asm("mov.b64 {%0, %1}, %2;" : "=f"(f.x), "=f"(f.y) : "l"(v)); return f;
}
__device__ __forceinline__ float red2(u64t a, u64t b) {
    float2 fa = up2(a), fb = up2(b);
    return (fa.x + fa.y) + (fb.x + fb.y);
}
__device__ __forceinline__ float red4(u64t a, u64t b, u64t c, u64t d) {
    float2 fa = up2(a), fb = up2(b), fc = up2(c), fd = up2(d);
    return ((fa.x + fa.y) + (fb.x + fb.y)) + ((fc.x + fc.y) + (fd.x + fd.y));
}

__device__ __forceinline__ float sigmf_(float x){ return __fdividef(1.0f, 1.0f + __expf(-x)); }
__device__ __forceinline__ float tanhf_(float x){ return 1.0f - __fdividef(2.0f, __expf(2.0f*x) + 1.0f); }
__device__ __forceinline__ float eluf_(float x){ return x>0.f ? x : (__expf(x) - 1.0f); }
__device__ __forceinline__ float lreluf_(float x){ return x>0.f ? x : 0.2f*x; }

// 16-j x 1-t slice of an xi GEMM: dst[q] = bias[j0+q] + W[j0+q] . src  (K=32)
__device__ __forceinline__ void xi_tile32(const float* __restrict__ W, const float* __restrict__ bias,
                                          const float* src, float* dst, int j0) {
    u64t acc[16];
    #pragma unroll
    for (int q = 0; q < 16; q++) acc[q] = 0ull;
    #pragma unroll
    for (int kc = 0; kc < 32; kc += 4) {
        ulonglong2 hv = *(const ulonglong2*)&src[kc];
        #pragma unroll
        for (int q = 0; q < 16; q++) {
            ulonglong2 wv = *(const ulonglong2*)&W[(j0+q)*32 + kc];
            fma2(acc[q], wv.x, hv.x);
            fma2(acc[q], wv.y, hv.y);
        }
    }
    #pragma unroll
    for (int q = 0; q < 16; q++) {
        float2 f = up2(acc[q]);
        dst[q] = bias[j0+q] + (f.x + f.y);
    }
}
// same with K=64
__device__ __forceinline__ void xi_tile64(const float* __restrict__ W, const float* __restrict__ bias,
                                          const float* src, float* dst, int j0) {
    u64t acc[16];
    #pragma unroll
    for (int q = 0; q < 16; q++) acc[q] = 0ull;
    #pragma unroll 4
    for (int kc = 0; kc < 64; kc += 4) {
        ulonglong2 hv = *(const ulonglong2*)&src[kc];
        #pragma unroll
        for (int q = 0; q < 16; q++) {
            ulonglong2 wv = *(const ulonglong2*)&W[(j0+q)*64 + kc];
            fma2(acc[q], wv.x, hv.x);
            fma2(acc[q], wv.y, hv.y);
        }
    }
    #pragma unroll
    for (int q = 0; q < 16; q++) {
        float2 f = up2(acc[q]);
        dst[q] = bias[j0+q] + (f.x + f.y);
    }
}

__global__ void __launch_bounds__(NTH, 2) fused_gatgru_kernel(
    const float* __restrict__ x,   const int*   __restrict__ ei,
    const float* __restrict__ W1,  const float* __restrict__ aS1,
    const float* __restrict__ aD1, const float* __restrict__ b1,
    const float* __restrict__ W2,  const float* __restrict__ aS2,
    const float* __restrict__ aD2, const float* __restrict__ b2,
    const float* __restrict__ gamma, const float* __restrict__ beta,
    const float* __restrict__ Wi1, const float* __restrict__ Wh1,
    const float* __restrict__ bi1, const float* __restrict__ bh1,
    const float* __restrict__ Wi2, const float* __restrict__ Wh2,
    const float* __restrict__ bi2, const float* __restrict__ bh2,
    const float* __restrict__ Wf,  const float* __restrict__ bf,
    float* __restrict__ out)
{
    extern __shared__ float sm[];
    int* smi = (int*)sm;
    const int tid = threadIdx.x;
    const int b   = blockIdx.x;

    // ---------------- Phase 0
    {
        const float4* xg = (const float4*)(x + b*NN*TIN);
        float4* xs = (float4*)&sm[O_X];
        if (tid < 96) xs[tid] = xg[tid];
    }
    for (int k = tid; k < ET; k += NTH) {
        int s, d;
        if (k < EPB) { s = ei[b*EPB + k] - b*NN; d = ei[E_ + b*EPB + k] - b*NN; }
        else         { s = d = k - EPB; }
        smi[O_SRC + k] = s; smi[O_DST + k] = d;
    }
    if (tid < NN) smi[O_CNT + tid] = 0;
    __syncthreads();

    // ---------------- Phase 1: h1 = x @ W1
    for (int jj = 0; jj < 2; jj++) {
        int j = tid + jj*NTH;
        int h = j >> 6, c = j & 63;
        u64t wp[6];
        #pragma unroll
        for (int k = 0; k < 6; k++)
            wp[k] = pk2(W1[(2*k)*HH + j], W1[(2*k+1)*HH + j]);
        for (int n = 0; n < NN; n++) {
            const u64t* xr = (const u64t*)&sm[O_X + n*TIN];
            u64t a0 = 0ull, a1 = 0ull;
            fma2(a0, xr[0], wp[0]);
            fma2(a1, xr[1], wp[1]);
            fma2(a0, xr[2], wp[2]);
            fma2(a1, xr[3], wp[3]);
            fma2(a0, xr[4], wp[4]);
            fma2(a1, xr[5], wp[5]);
            sm[O_H1 + (n*8 + h)*RS + c] = red2(a0, a1);
        }
    }
    for (int k = tid; k < ET; k += NTH)
        smi[O_SLOT + k] = atomicAdd(&smi[O_CNT + smi[O_DST + k]], 1);
    __syncthreads();

    // ---------------- Phase 2: es/ed dots + prefix sum
    {
        int n = tid >> 3, h = tid & 7;
        const ulonglong2* hr = (const ulonglong2*)&sm[O_H1 + (n*8 + h)*RS];
        const ulonglong2* as = (const ulonglong2*)(aS1 + h*HID);
        const ulonglong2* ad = (const ulonglong2*)(aD1 + h*HID);
        u64t e0 = 0ull, e1 = 0ull, d0 = 0ull, d1 = 0ull;
        #pragma unroll
        for (int kk = 0; kk < 16; kk++) {
            ulonglong2 v = hr[kk], a = as[kk], g = ad[kk];
            fma2(e0, v.x, a.x);
            fma2(e1, v.y, a.y);
            fma2(d0, v.x, g.x);
            fma2(d1, v.y, g.y);
        }
        sm[O_ES + n*8 + h] = red2(e0, e1);
        sm[O_ED + n*8 + h] = red2(d0, d1);
    }
    if (tid == 0) {
        int acc = 0;
        for (int d = 0; d < NN; d++) { smi[O_OFF + d] = acc; acc += smi[O_CNT + d]; }
        smi[O_OFF + NN] = acc;
    }
    __syncthreads();

    // ---------------- Phase 3: edge scores + CSR scatter
    for (int k = tid; k < ET; k += NTH) {
        int s = smi[O_SRC + k], d = smi[O_DST + k];
        const float4* es = (const float4*)&sm[O_ES + s*8];
        const float4* ed = (const float4*)&sm[O_ED + d*8];
        float4* eo = (float4*)&sm[O_E + k*8];
        float4 a0 = es[0], a1 = es[1], b0 = ed[0], b1 = ed[1];
        float4 r0, r1;
        r0.x = lreluf_(a0.x + b0.x); r0.y = lreluf_(a0.y + b0.y);
        r0.z = lreluf_(a0.z + b0.z); r0.w = lreluf_(a0.w + b0.w);
        r1.x = lreluf_(a1.x + b1.x); r1.y = lreluf_(a1.y + b1.y);
        r1.z = lreluf_(a1.z + b1.z); r1.w = lreluf_(a1.w + b1.w);
        eo[0] = r0; eo[1] = r1;
    }
    for (int k = tid; k < ET; k += NTH)
        smi[O_CSR + smi[O_OFF + smi[O_DST + k]] + smi[O_SLOT + k]] = k;
    __syncthreads();

    // ---------------- Phase 4: GAT1 softmax + aggregation
    {
        int dst = tid >> 3, h = tid & 7;
        int o   = smi[O_OFF + dst], deg = smi[O_OFF + dst + 1] - o;
        float m = -1e30f;
        for (int i = 0; i < deg; i++)
            m = fmaxf(m, sm[O_E + smi[O_CSR + o + i]*8 + h]);
        float s = 0.f;
        for (int i = 0; i < deg; i++) {
            int k = smi[O_CSR + o + i];
            float p = __expf(sm[O_E + k*8 + h] - m);
            sm[O_E + k*8 + h] = p;
            s += p;
        }
        float inv = __fdividef(1.f, s + 1e-16f);
        u64t acc[32];
        #pragma unroll
        for (int j = 0; j < 32; j++) acc[j] = 0ull;
        for (int i = 0; i < deg; i++) {
            int k = smi[O_CSR + o + i];
            u64t pp = pk2(sm[O_E + k*8 + h], sm[O_E + k*8 + h]);
            const ulonglong2* hr = (const ulonglong2*)&sm[O_H1 + (smi[O_SRC + k]*8 + h)*RS];
            #pragma unroll
            for (int j = 0; j < 16; j++) {
                ulonglong2 v = hr[j];
                fma2(acc[2*j],   pp, v.x);
                fma2(acc[2*j+1], pp, v.y);
            }
        }
        __syncthreads();
        float4* orow = (float4*)&sm[O_H1 + (dst*8 + h)*RS];
        const float4* bb = (const float4*)(b1 + h*HID);
        #pragma unroll
        for (int j = 0; j < 16; j++) {
            float4 bv = bb[j], r;
            float2 lo = up2(acc[2*j]), hi = up2(acc[2*j+1]);
            r.x = eluf_(fmaf(lo.x, inv, bv.x));
            r.y = eluf_(fmaf(lo.y, inv, bv.y));
            r.z = eluf_(fmaf(hi.x, inv, bv.z));
            r.w = eluf_(fmaf(hi.y, inv, bv.w));
            orow[j] = r;
        }
    }
    __syncthreads();

    // ---------------- Phase 5: h2 = out1 @ W2
    {
        int c = tid & 63, grp = tid >> 6;
        u64t accA[8], accB[8];
        #pragma unroll
        for (int i = 0; i < 8; i++) { accA[i] = 0ull; accB[i] = 0ull; }
        for (int hd = 0; hd < 8; hd++) {
            const float* w2p = W2 + hd*64*HID + c;
            #pragma unroll 4
            for (int kc = 0; kc < 64; kc += 4) {
                u64t wA = pk2(w2p[(kc+0)*HID], w2p[(kc+1)*HID]);
                u64t wB = pk2(w2p[(kc+2)*HID], w2p[(kc+3)*HID]);
                #pragma unroll
                for (int i = 0; i < 8; i++) {
                    ulonglong2 v = *(const ulonglong2*)&sm[O_H1 + ((grp*8+i)*8 + hd)*RS + kc];
                    fma2(accA[i], v.x, wA);
                    fma2(accB[i], v.y, wB);
                }
            }
        }
        #pragma unroll
        for (int i = 0; i < 8; i++)
            sm[O_H2 + (grp*8+i)*H2S + c] = red2(accA[i], accB[i]);
    }
    __syncthreads();

    // ---------------- Phase 6: GAT2 attention
    if (tid < 64) {
        int n = tid & 31;
        const ulonglong2* a  = (const ulonglong2*)((tid < 32) ? aS2 : aD2);
        const ulonglong2* hr = (const ulonglong2*)&sm[O_H2 + n*H2S];
        u64t a0 = 0ull, a1 = 0ull;
        #pragma unroll
        for (int kk = 0; kk < 16; kk++) {
            ulonglong2 v = hr[kk], w = a[kk];
            fma2(a0, v.x, w.x);
            fma2(a1, v.y, w.y);
        }
        sm[(tid < 32 ? O_ES2 : O_ED2) + n] = red2(a0, a1);
    }
    __syncthreads();
    for (int k = tid; k < ET; k += NTH)
        sm[O_E2 + k] = lreluf_(sm[O_ES2 + smi[O_SRC + k]] + sm[O_ED2 + smi[O_DST + k]]);
    __syncthreads();
    if (tid < NN) {
        int o = smi[O_OFF + tid], deg = smi[O_OFF + tid + 1] - o;
        float m = -1e30f;
        for (int i = 0; i < deg; i++) m = fmaxf(m, sm[O_E2 + smi[O_CSR + o + i]]);
        float s = 0.f;
        for (int i = 0; i < deg; i++) s += __expf(sm[O_E2 + smi[O_CSR + o + i]] - m);
        sm[O_M2 + tid]  = m;
        sm[O_IS2 + tid] = __fdividef(1.f, s + 1e-16f);
    }
    __syncthreads();
    for (int k = tid; k < ET; k += NTH) {
        int d = smi[O_DST + k];
        sm[O_AL2 + k] = __expf(sm[O_E2 + k] - sm[O_M2 + d]) * sm[O_IS2 + d];
    }
    __syncthreads();
    {
        int dst = tid >> 3, cc = (tid & 7) * 8;
        int o = smi[O_OFF + dst], deg = smi[O_OFF + dst + 1] - o;
        u64t a0 = 0ull, a1 = 0ull, a2 = 0ull, a3 = 0ull;
        for (int i = 0; i < deg; i++) {
            int k = smi[O_CSR + o + i];
            float al = sm[O_AL2 + k];
            u64t pp = pk2(al, al);
            const ulonglong2* hr = (const ulonglong2*)&sm[O_H2 + smi[O_SRC + k]*H2S + cc];
            ulonglong2 v0 = hr[0], v1 = hr[1];
            fma2(a0, pp, v0.x);
            fma2(a1, pp, v0.y);
            fma2(a2, pp, v1.x);
            fma2(a3, pp, v1.y);
        }
        const float4* bb = (const float4*)(b2 + cc);
        float4 b0 = bb[0], b1v = bb[1], r0, r1;
        float2 f0 = up2(a0), f1 = up2(a1), f2 = up2(a2), f3 = up2(a3);
        r0.x = eluf_(f0.x + b0.x); r0.y = eluf_(f0.y + b0.y);
        r0.z = eluf_(f1.x + b0.z); r0.w = eluf_(f1.y + b0.w);
        r1.x = eluf_(f2.x + b1v.x); r1.y = eluf_(f2.y + b1v.y);
        r1.z = eluf_(f3.x + b1v.z); r1.w = eluf_(f3.y + b1v.w);
        float4* g = (float4*)&sm[O_G2 + dst*H2S + cc];
        g[0] = r0; g[1] = r1;
    }
    __syncthreads();

    // ---------------- Phase 7: LayerNorm + transpose -> hlnT[t][n]
    if (tid < NN) {
        const float4* r4 = (const float4*)&sm[O_G2 + tid*H2S];
        float4 row[16];
        float mu = 0.f;
        #pragma unroll
        for (int kk = 0; kk < 16; kk++) {
            row[kk] = r4[kk];
            mu += (row[kk].x + row[kk].y) + (row[kk].z + row[kk].w);
        }
        mu *= (1.f/HID);
        float var = 0.f;
        #pragma unroll
        for (int kk = 0; kk < 16; kk++) {
            float dx = row[kk].x-mu, dy = row[kk].y-mu, dz = row[kk].z-mu, dw = row[kk].w-mu;
            var += fmaf(dx,dx, dy*dy) + fmaf(dz,dz, dw*dw);
        }
        var *= (1.f/HID);
        float is = rsqrtf(var + 1e-5f);
        #pragma unroll
        for (int kk = 0; kk < 16; kk++) {
            int t = kk*4;
            sm[O_HLNT + (t+0)*HLNTS + tid] = (row[kk].x - mu)*is*gamma[t+0] + beta[t+0];
            sm[O_HLNT + (t+1)*HLNTS + tid] = (row[kk].y - mu)*is*gamma[t+1] + beta[t+1];
            sm[O_HLNT + (t+2)*HLNTS + tid] = (row[kk].z - mu)*is*gamma[t+2] + beta[t+2];
            sm[O_HLNT + (t+3)*HLNTS + tid] = (row[kk].w - mu)*is*gamma[t+3] + beta[t+3];
        }
    }
    __syncthreads();

    const int wrp  = tid >> 5;
    const int lane = tid & 31;

    // ---------------- Phase 8a: xi1 chunk0 (t=0..31), all 8 warps
    for (int tile = wrp; tile < 12; tile += 8) {
        int t = lane;
        xi_tile32(Wi1, bi1, &sm[O_HLNT + t*HLNTS], &sm[O_XI + t*XIS + tile*16], tile*16);
    }
    // Wh1 rows into registers (warps 0-5)
    u64t wh2[32]; float bh = 0.f;
    if (tid < 192) {
        bh = bh1[tid];
        const ulonglong2* w = (const ulonglong2*)(Wh1 + tid*HID);
        #pragma unroll
        for (int kk = 0; kk < 16; kk++) {
            ulonglong2 t = w[kk];
            wh2[2*kk]   = t.x;
            wh2[2*kk+1] = t.y;
        }
    }
    if (tid < HID) sm[O_HSM + tid] = 0.f;
    __syncthreads();

    // ---------------- Phase 9: GRU1 recurrence + overlapped xi1 chunk1 / xi2 chunk0
    {
        float h_reg = 0.f;
        if (wrp < 6) {
            for (int t = 0; t < HID; t++) {
                if (t == 32) BAR_SYNC(4, 256);        // xi1 chunk1 ready; xi1[0..31] consumed
                const ulonglong2* h4 = (const ulonglong2*)&sm[O_HSM];
                u64t a0 = 0ull, a1 = 0ull, a2 = 0ull, a3 = 0ull;
                #pragma unroll
                for (int kk = 0; kk < 8; kk++) {
                    ulonglong2 v0 = h4[2*kk], v1 = h4[2*kk+1];
                    fma2(a0, wh2[4*kk],   v0.x);
                    fma2(a1, wh2[4*kk+1], v0.y);
                    fma2(a2, wh2[4*kk+2], v1.x);
                    fma2(a3, wh2[4*kk+3], v1.y);
                }
                float gh = bh + red4(a0, a1, a2, a3);
                if (wrp >= 2) {
                    sm[O_GH + tid] = gh;
                    BAR_ARRIVE(1, 192);               // gh ready
                    BAR_SYNC(2, 192);                 // wait h update
                } else {
                    BAR_SYNC(1, 192);                 // wait all gh (r-gate gh stays in reg)
                    const float* xr = &sm[O_XI + t*XIS];
                    float r  = sigmf_(xr[tid]       + gh);
                    float z  = sigmf_(xr[64 + tid]  + sm[O_GH + 64 + tid]);
                    float nv = tanhf_(fmaf(r, sm[O_GH + 128 + tid], xr[128 + tid]));
                    float hn = (1.f - z)*nv + z*h_reg;
                    h_reg = hn;
                    sm[O_HSM + tid]        = hn;
                    sm[O_YS + t*YSS + tid] = hn;
                    BAR_ARRIVE(2, 192);               // h ready for matvec warps
                    BAR_SYNC(3, 64);                  // act warps mutually synced
                }
            }
        } else {
            // warps 6-7: xi1 chunk1 (t=32..63) during steps 0..31
            for (int tile = wrp - 6; tile < 12; tile += 2) {
                int t = 32 + lane;
                xi_tile32(Wi1, bi1, &sm[O_HLNT + t*HLNTS], &sm[O_XI + t*XIS + tile*16], tile*16);
            }
            BAR_SYNC(4, 256);                         // rendezvous at t=32
            // xi2 chunk0 (t=0..31) during steps 32..63; overwrites dead xi1 rows
            for (int tile = wrp - 6; tile < 12; tile += 2) {
                int t = lane;
                xi_tile64(Wi2, bi2, &sm[O_YS + t*YSS], &sm[O_XI + t*XIS + tile*16], tile*16);
            }
        }
    }
    __syncthreads();

    // ---------------- Phase 10: xi2 chunk1 (t=32..63), all 8 warps
    for (int tile = wrp; tile < 12; tile += 8) {
        int t = 32 + lane;
        xi_tile64(Wi2, bi2, &sm[O_YS + t*YSS], &sm[O_XI + t*XIS + tile*16], tile*16);
    }
    if (tid < 192) {
        bh = bh2[tid];
        const ulonglong2* w = (const ulonglong2*)(Wh2 + tid*HID);
        #pragma unroll
        for (int kk = 0; kk < 16; kk++) {
            ulonglong2 t = w[kk];
            wh2[2*kk]   = t.x;
            wh2[2*kk+1] = t.y;
        }
    }
    if (tid < HID) sm[O_HSM + tid] = 0.f;
    __syncthreads();

    // ---------------- Phase 11: GRU2 recurrence (final h only)
    {
        float h_reg = 0.f;
        if (wrp < 6) {
            for (int t = 0; t < HID; t++) {
                const ulonglong2* h4 = (const ulonglong2*)&sm[O_HSM];
                u64t a0 = 0ull, a1 = 0ull, a2 = 0ull, a3 = 0ull;
                #pragma unroll
                for (int kk = 0; kk < 8; kk++) {
                    ulonglong2 v0 = h4[2*kk], v1 = h4[2*kk+1];
                    fma2(a0, wh2[4*kk],   v0.x);
                    fma2(a1, wh2[4*kk+1], v0.y);
                    fma2(a2, wh2[4*kk+2], v1.x);
                    fma2(a3, wh2[4*kk+3], v1.y);
                }
                float gh = bh + red4(a0, a1, a2, a3);
                if (wrp >= 2) {
                    sm[O_GH + tid] = gh;
                    BAR_ARRIVE(1, 192);
                    BAR_SYNC(2, 192);
                } else {
                    BAR_SYNC(1, 192);
                    const float* xr = &sm[O_XI + t*XIS];
                    float r  = sigmf_(xr[tid]       + gh);
                    float z  = sigmf_(xr[64 + tid]  + sm[O_GH + 64 + tid]);
                    float nv = tanhf_(fmaf(r, sm[O_GH + 128 + tid], xr[128 + tid]));
                    float hn = (1.f - z)*nv + z*h_reg;
                    h_reg = hn;
                    sm[O_HSM + tid] = hn;
                    BAR_ARRIVE(2, 192);
                    BAR_SYNC(3, 64);
                }
            }
        }
    }
    __syncthreads();

    // ---------------- Phase 12: final linear
    if (tid < 9) {
        const ulonglong2* w = (const ulonglong2*)(Wf + tid*HID);
        const ulonglong2* h4 = (const ulonglong2*)&sm[O_HSM];
        u64t a0 = 0ull, a1 = 0ull;
        #pragma unroll
        for (int kk = 0; kk < 16; kk++) {
            ulonglong2 wv = w[kk], hv = h4[kk];
            fma2(a0, wv.x, hv.x);
            fma2(a1, wv.y, hv.y);
        }
        out[b*9 + tid] = bf[tid] + red2(a0, a1);
    }
}

extern "C" void kernel_launch(void* const* d_in, const int* in_sizes, int n_in,
                              void* d_out, int out_size) {
    (void)in_sizes; (void)n_in; (void)out_size;
    const float* x    = (const float*)d_in[0];
    const int*   ei   = (const int*)  d_in[1];
    const float* W1   = (const float*)d_in[2];
    const float* aS1  = (const float*)d_in[3];
    const float* aD1  = (const float*)d_in[4];
    const float* b1   = (const float*)d_in[5];
    const float* W2   = (const float*)d_in[6];
    const float* aS2  = (const float*)d_in[7];
    const float* aD2  = (const float*)d_in[8];
    const float* b2   = (const float*)d_in[9];
    const float* gam  = (const float*)d_in[10];
    const float* bet  = (const float*)d_in[11];
    const float* Wi1  = (const float*)d_in[12];
    const float* Wh1  = (const float*)d_in[13];
    const float* bi1  = (const float*)d_in[14];
    const float* bh1  = (const float*)d_in[15];
    const float* Wi2  = (const float*)d_in[16];
    const float* Wh2  = (const float*)d_in[17];
    const float* bi2  = (const float*)d_in[18];
    const float* bh2  = (const float*)d_in[19];
    const float* Wf   = (const float*)d_in[20];
    const float* bf   = (const float*)d_in[21];
    float* out = (float*)d_out;

    size_t smem = (size_t)SMEM_FLOATS * sizeof(float);
    cudaFuncSetAttribute(fused_gatgru_kernel,
                         cudaFuncAttributeMaxDynamicSharedMemorySize, (int)smem);
    fused_gatgru_kernel<<<512, NTH, smem>>>(
        x, ei, W1, aS1, aD1, b1, W2, aS2, aD2, b2, gam, bet,
        Wi1, Wh1, bi1, bh1, Wi2, Wh2, bi2, bh2, Wf, bf, out);
}

// round 8
// speedup vs baseline: 1.1917x; 1.1917x over previous
#include <cuda_runtime.h>
#include <math.h>

#define NN     32
#define TIN    12
#define HID    64
#define HEADS  8
#define HH     512
#define EPB    256
#define ET     288
#define E_     131072
#define NTH    256
#define RS     68
#define H2S    68
#define HLNTS  36
#define XIS    196
#define YSS    68

#define O_H1    0
#define O_XI    0
#define O_YS    12544
#define O_X     17408
#define O_ES2   17408
#define O_ED2   17440
#define O_M2    17472
#define O_IS2   17504
#define O_AL2   17536
#define O_ES    17792
#define O_E2    17824
#define O_ED    18048
#define O_E     18304
#define O_HLNT  18304
#define O_SRC   20608
#define O_DST   20896
#define O_CNT   21184
#define O_OFF   21216
#define O_SLOT  21249
#define O_CSR   21537
#define O_H2    21828
#define O_G2    24004
#define O_HSM   24004
#define O_GH    24068
#define SMEM_FLOATS 26180

typedef unsigned long long u64t;

#define BAR_SYNC(id, n) asm volatile("bar.sync %0, %1;" :: "n"(id), "n"(n) : "memory")

__device__ __forceinline__ u64t pk2(float lo, float hi) {
    u64t r; asm("mov.b64 %0, {%1, %2};" : "=l"(r) : "f"(lo), "f"(hi)); return r;
}
__device__ __forceinline__ void fma2(u64t& d, u64t a, u64t b) {
    asm("fma.rn.f32x2 %0, %1, %2, %3;" : "=l"(d) : "l"(a), "l"(b), "l"(d));
}
__device__ __forceinline__ float2 up2(u64t v) {
    float2 f; asm("mov.b64 {%0, %1}, %2;" : "=f"(f.x), "=f"(f.y) : "l"(v)); return f;
}
__device__ __forceinline__ float red2(u64t a, u64t b) {
    float2 fa = up2(a), fb = up2(b);
    return (fa.x + fa.y) + (fb.x + fb.y);
}
__device__ __forceinline__ float red4(u64t a, u64t b, u64t c, u64t d) {
    float2 fa = up2(a), fb = up2(b), fc = up2(c), fd = up2(d);
    return ((fa.x + fa.y) + (fb.x + fb.y)) + ((fc.x + fc.y) + (fd.x + fd.y));
}

__device__ __forceinline__ float sigmf_(float x){ return __fdividef(1.0f, 1.0f + __expf(-x)); }
__device__ __forceinline__ float tanhf_(float x){ return 1.0f - __fdividef(2.0f, __expf(2.0f*x) + 1.0f); }
__device__ __forceinline__ float eluf_(float x){ return x>0.f ? x : (__expf(x) - 1.0f); }
__device__ __forceinline__ float lreluf_(float x){ return x>0.f ? x : 0.2f*x; }

__device__ __forceinline__ void xi_tile32(const float* __restrict__ W, const float* __restrict__ bias,
                                          const float* src, float* dst, int j0) {
    u64t acc[16];
    #pragma unroll
    for (int q = 0; q < 16; q++) acc[q] = 0ull;
    #pragma unroll
    for (int kc = 0; kc < 32; kc += 4) {
        ulonglong2 hv = *(const ulonglong2*)&src[kc];
        #pragma unroll
        for (int q = 0; q < 16; q++) {
            ulonglong2 wv = *(const ulonglong2*)&W[(j0+q)*32 + kc];
            fma2(acc[q], wv.x, hv.x);
            fma2(acc[q], wv.y, hv.y);
        }
    }
    #pragma unroll
    for (int q = 0; q < 16; q++) {
        float2 f = up2(acc[q]);
        dst[q] = bias[j0+q] + (f.x + f.y);
    }
}
__device__ __forceinline__ void xi_tile64(const float* __restrict__ W, const float* __restrict__ bias,
                                          const float* src, float* dst, int j0) {
    u64t acc[16];
    #pragma unroll
    for (int q = 0; q < 16; q++) acc[q] = 0ull;
    #pragma unroll 4
    for (int kc = 0; kc < 64; kc += 4) {
        ulonglong2 hv = *(const ulonglong2*)&src[kc];
        #pragma unroll
        for (int q = 0; q < 16; q++) {
            ulonglong2 wv = *(const ulonglong2*)&W[(j0+q)*64 + kc];
            fma2(acc[q], wv.x, hv.x);
            fma2(acc[q], wv.y, hv.y);
        }
    }
    #pragma unroll
    for (int q = 0; q < 16; q++) {
        float2 f = up2(acc[q]);
        dst[q] = bias[j0+q] + (f.x + f.y);
    }
}

__global__ void __launch_bounds__(NTH, 2) fused_gatgru_kernel(
    const float* __restrict__ x,   const int*   __restrict__ ei,
    const float* __restrict__ W1,  const float* __restrict__ aS1,
    const float* __restrict__ aD1, const float* __restrict__ b1,
    const float* __restrict__ W2,  const float* __restrict__ aS2,
    const float* __restrict__ aD2, const float* __restrict__ b2,
    const float* __restrict__ gamma, const float* __restrict__ beta,
    const float* __restrict__ Wi1, const float* __restrict__ Wh1,
    const float* __restrict__ bi1, const float* __restrict__ bh1,
    const float* __restrict__ Wi2, const float* __restrict__ Wh2,
    const float* __restrict__ bi2, const float* __restrict__ bh2,
    const float* __restrict__ Wf,  const float* __restrict__ bf,
    float* __restrict__ out)
{
    extern __shared__ float sm[];
    int* smi = (int*)sm;
    const int tid = threadIdx.x;
    const int b   = blockIdx.x;

    // ---------------- Phase 0
    {
        const float4* xg = (const float4*)(x + b*NN*TIN);
        float4* xs = (float4*)&sm[O_X];
        if (tid < 96) xs[tid] = xg[tid];
    }
    for (int k = tid; k < ET; k += NTH) {
        int s, d;
        if (k < EPB) { s = ei[b*EPB + k] - b*NN; d = ei[E_ + b*EPB + k] - b*NN; }
        else         { s = d = k - EPB; }
        smi[O_SRC + k] = s; smi[O_DST + k] = d;
    }
    if (tid < NN) smi[O_CNT + tid] = 0;
    __syncthreads();

    // ---------------- Phase 1: h1 = x @ W1
    for (int jj = 0; jj < 2; jj++) {
        int j = tid + jj*NTH;
        int h = j >> 6, c = j & 63;
        u64t wp[6];
        #pragma unroll
        for (int k = 0; k < 6; k++)
            wp[k] = pk2(W1[(2*k)*HH + j], W1[(2*k+1)*HH + j]);
        for (int n = 0; n < NN; n++) {
            const u64t* xr = (const u64t*)&sm[O_X + n*TIN];
            u64t a0 = 0ull, a1 = 0ull;
            fma2(a0, xr[0], wp[0]);
            fma2(a1, xr[1], wp[1]);
            fma2(a0, xr[2], wp[2]);
            fma2(a1, xr[3], wp[3]);
            fma2(a0, xr[4], wp[4]);
            fma2(a1, xr[5], wp[5]);
            sm[O_H1 + (n*8 + h)*RS + c] = red2(a0, a1);
        }
    }
    for (int k = tid; k < ET; k += NTH)
        smi[O_SLOT + k] = atomicAdd(&smi[O_CNT + smi[O_DST + k]], 1);
    __syncthreads();

    // ---------------- Phase 2: es/ed dots + prefix sum
    {
        int n = tid >> 3, h = tid & 7;
        const ulonglong2* hr = (const ulonglong2*)&sm[O_H1 + (n*8 + h)*RS];
        const ulonglong2* as = (const ulonglong2*)(aS1 + h*HID);
        const ulonglong2* ad = (const ulonglong2*)(aD1 + h*HID);
        u64t e0 = 0ull, e1 = 0ull, d0 = 0ull, d1 = 0ull;
        #pragma unroll
        for (int kk = 0; kk < 16; kk++) {
            ulonglong2 v = hr[kk], a = as[kk], g = ad[kk];
            fma2(e0, v.x, a.x);
            fma2(e1, v.y, a.y);
            fma2(d0, v.x, g.x);
            fma2(d1, v.y, g.y);
        }
        sm[O_ES + n*8 + h] = red2(e0, e1);
        sm[O_ED + n*8 + h] = red2(d0, d1);
    }
    if (tid == 0) {
        int acc = 0;
        for (int d = 0; d < NN; d++) { smi[O_OFF + d] = acc; acc += smi[O_CNT + d]; }
        smi[O_OFF + NN] = acc;
    }
    __syncthreads();

    // ---------------- Phase 3: edge scores + CSR scatter
    for (int k = tid; k < ET; k += NTH) {
        int s = smi[O_SRC + k], d = smi[O_DST + k];
        const float4* es = (const float4*)&sm[O_ES + s*8];
        const float4* ed = (const float4*)&sm[O_ED + d*8];
        float4* eo = (float4*)&sm[O_E + k*8];
        float4 a0 = es[0], a1 = es[1], b0 = ed[0], b1 = ed[1];
        float4 r0, r1;
        r0.x = lreluf_(a0.x + b0.x); r0.y = lreluf_(a0.y + b0.y);
        r0.z = lreluf_(a0.z + b0.z); r0.w = lreluf_(a0.w + b0.w);
        r1.x = lreluf_(a1.x + b1.x); r1.y = lreluf_(a1.y + b1.y);
        r1.z = lreluf_(a1.z + b1.z); r1.w = lreluf_(a1.w + b1.w);
        eo[0] = r0; eo[1] = r1;
    }
    for (int k = tid; k < ET; k += NTH)
        smi[O_CSR + smi[O_OFF + smi[O_DST + k]] + smi[O_SLOT + k]] = k;
    __syncthreads();

    // ---------------- Phase 4: GAT1 softmax + aggregation
    {
        int dst = tid >> 3, h = tid & 7;
        int o   = smi[O_OFF + dst], deg = smi[O_OFF + dst + 1] - o;
        float m = -1e30f;
        for (int i = 0; i < deg; i++)
            m = fmaxf(m, sm[O_E + smi[O_CSR + o + i]*8 + h]);
        float s = 0.f;
        for (int i = 0; i < deg; i++) {
            int k = smi[O_CSR + o + i];
            float p = __expf(sm[O_E + k*8 + h] - m);
            sm[O_E + k*8 + h] = p;
            s += p;
        }
        float inv = __fdividef(1.f, s + 1e-16f);
        u64t acc[32];
        #pragma unroll
        for (int j = 0; j < 32; j++) acc[j] = 0ull;
        for (int i = 0; i < deg; i++) {
            int k = smi[O_CSR + o + i];
            u64t pp = pk2(sm[O_E + k*8 + h], sm[O_E + k*8 + h]);
            const ulonglong2* hr = (const ulonglong2*)&sm[O_H1 + (smi[O_SRC + k]*8 + h)*RS];
            #pragma unroll
            for (int j = 0; j < 16; j++) {
                ulonglong2 v = hr[j];
                fma2(acc[2*j],   pp, v.x);
                fma2(acc[2*j+1], pp, v.y);
            }
        }
        __syncthreads();
        float4* orow = (float4*)&sm[O_H1 + (dst*8 + h)*RS];
        const float4* bb = (const float4*)(b1 + h*HID);
        #pragma unroll
        for (int j = 0; j < 16; j++) {
            float4 bv = bb[j], r;
            float2 lo = up2(acc[2*j]), hi = up2(acc[2*j+1]);
            r.x = eluf_(fmaf(lo.x, inv, bv.x));
            r.y = eluf_(fmaf(lo.y, inv, bv.y));
            r.z = eluf_(fmaf(hi.x, inv, bv.z));
            r.w = eluf_(fmaf(hi.y, inv, bv.w));
            orow[j] = r;
        }
    }
    __syncthreads();

    // ---------------- Phase 5: h2 = out1 @ W2
    {
        int c = tid & 63, grp = tid >> 6;
        u64t accA[8], accB[8];
        #pragma unroll
        for (int i = 0; i < 8; i++) { accA[i] = 0ull; accB[i] = 0ull; }
        for (int hd = 0; hd < 8; hd++) {
            const float* w2p = W2 + hd*64*HID + c;
            #pragma unroll 4
            for (int kc = 0; kc < 64; kc += 4) {
                u64t wA = pk2(w2p[(kc+0)*HID], w2p[(kc+1)*HID]);
                u64t wB = pk2(w2p[(kc+2)*HID], w2p[(kc+3)*HID]);
                #pragma unroll
                for (int i = 0; i < 8; i++) {
                    ulonglong2 v = *(const ulonglong2*)&sm[O_H1 + ((grp*8+i)*8 + hd)*RS + kc];
                    fma2(accA[i], v.x, wA);
                    fma2(accB[i], v.y, wB);
                }
            }
        }
        #pragma unroll
        for (int i = 0; i < 8; i++)
            sm[O_H2 + (grp*8+i)*H2S + c] = red2(accA[i], accB[i]);
    }
    __syncthreads();

    // ---------------- Phase 6: GAT2 attention
    if (tid < 64) {
        int n = tid & 31;
        const ulonglong2* a  = (const ulonglong2*)((tid < 32) ? aS2 : aD2);
        const ulonglong2* hr = (const ulonglong2*)&sm[O_H2 + n*H2S];
        u64t a0 = 0ull, a1 = 0ull;
        #pragma unroll
        for (int kk = 0; kk < 16; kk++) {
            ulonglong2 v = hr[kk], w = a[kk];
            fma2(a0, v.x, w.x);
            fma2(a1, v.y, w.y);
        }
        sm[(tid < 32 ? O_ES2 : O_ED2) + n] = red2(a0, a1);
    }
    __syncthreads();
    for (int k = tid; k < ET; k += NTH)
        sm[O_E2 + k] = lreluf_(sm[O_ES2 + smi[O_SRC + k]] + sm[O_ED2 + smi[O_DST + k]]);
    __syncthreads();
    if (tid < NN) {
        int o = smi[O_OFF + tid], deg = smi[O_OFF + tid + 1] - o;
        float m = -1e30f;
        for (int i = 0; i < deg; i++) m = fmaxf(m, sm[O_E2 + smi[O_CSR + o + i]]);
        float s = 0.f;
        for (int i = 0; i < deg; i++) s += __expf(sm[O_E2 + smi[O_CSR + o + i]] - m);
        sm[O_M2 + tid]  = m;
        sm[O_IS2 + tid] = __fdividef(1.f, s + 1e-16f);
    }
    __syncthreads();
    for (int k = tid; k < ET; k += NTH) {
        int d = smi[O_DST + k];
        sm[O_AL2 + k] = __expf(sm[O_E2 + k] - sm[O_M2 + d]) * sm[O_IS2 + d];
    }
    __syncthreads();
    {
        int dst = tid >> 3, cc = (tid & 7) * 8;
        int o = smi[O_OFF + dst], deg = smi[O_OFF + dst + 1] - o;
        u64t a0 = 0ull, a1 = 0ull, a2 = 0ull, a3 = 0ull;
        for (int i = 0; i < deg; i++) {
            int k = smi[O_CSR + o + i];
            float al = sm[O_AL2 + k];
            u64t pp = pk2(al, al);
            const ulonglong2* hr = (const ulonglong2*)&sm[O_H2 + smi[O_SRC + k]*H2S + cc];
            ulonglong2 v0 = hr[0], v1 = hr[1];
            fma2(a0, pp, v0.x);
            fma2(a1, pp, v0.y);
            fma2(a2, pp, v1.x);
            fma2(a3, pp, v1.y);
        }
        const float4* bb = (const float4*)(b2 + cc);
        float4 b0 = bb[0], b1v = bb[1], r0, r1;
        float2 f0 = up2(a0), f1 = up2(a1), f2 = up2(a2), f3 = up2(a3);
        r0.x = eluf_(f0.x + b0.x); r0.y = eluf_(f0.y + b0.y);
        r0.z = eluf_(f1.x + b0.z); r0.w = eluf_(f1.y + b0.w);
        r1.x = eluf_(f2.x + b1v.x); r1.y = eluf_(f2.y + b1v.y);
        r1.z = eluf_(f3.x + b1v.z); r1.w = eluf_(f3.y + b1v.w);
        float4* g = (float4*)&sm[O_G2 + dst*H2S + cc];
        g[0] = r0; g[1] = r1;
    }
    __syncthreads();

    // ---------------- Phase 7: LayerNorm + transpose -> hlnT[t][n]
    if (tid < NN) {
        const float4* r4 = (const float4*)&sm[O_G2 + tid*H2S];
        float4 row[16];
        float mu = 0.f;
        #pragma unroll
        for (int kk = 0; kk < 16; kk++) {
            row[kk] = r4[kk];
            mu += (row[kk].x + row[kk].y) + (row[kk].z + row[kk].w);
        }
        mu *= (1.f/HID);
        float var = 0.f;
        #pragma unroll
        for (int kk = 0; kk < 16; kk++) {
            float dx = row[kk].x-mu, dy = row[kk].y-mu, dz = row[kk].z-mu, dw = row[kk].w-mu;
            var += fmaf(dx,dx, dy*dy) + fmaf(dz,dz, dw*dw);
        }
        var *= (1.f/HID);
        float is = rsqrtf(var + 1e-5f);
        #pragma unroll
        for (int kk = 0; kk < 16; kk++) {
            int t = kk*4;
            sm[O_HLNT + (t+0)*HLNTS + tid] = (row[kk].x - mu)*is*gamma[t+0] + beta[t+0];
            sm[O_HLNT + (t+1)*HLNTS + tid] = (row[kk].y - mu)*is*gamma[t+1] + beta[t+1];
            sm[O_HLNT + (t+2)*HLNTS + tid] = (row[kk].z - mu)*is*gamma[t+2] + beta[t+2];
            sm[O_HLNT + (t+3)*HLNTS + tid] = (row[kk].w - mu)*is*gamma[t+3] + beta[t+3];
        }
    }
    __syncthreads();

    const int wrp  = tid >> 5;
    const int lane = tid & 31;

    // ---------------- Phase 8a: xi1 chunk0 (t=0..31), all 8 warps
    for (int tile = wrp; tile < 12; tile += 8) {
        int t = lane;
        xi_tile32(Wi1, bi1, &sm[O_HLNT + t*HLNTS], &sm[O_XI + t*XIS + tile*16], tile*16);
    }
    // Wh1 row j=tid-64 into registers (warps 2-7)
    u64t wh2[32]; float bh = 0.f;
    if (wrp >= 2) {
        int j = tid - 64;
        bh = bh1[j];
        const ulonglong2* w = (const ulonglong2*)(Wh1 + j*HID);
        #pragma unroll
        for (int kk = 0; kk < 16; kk++) {
            ulonglong2 t = w[kk];
            wh2[2*kk]   = t.x;
            wh2[2*kk+1] = t.y;
        }
    }
    if (tid < HID) sm[O_HSM + tid] = 0.f;
    __syncthreads();

    // ---------------- Phase 9: GRU1 (matvec warps 2-7, act warps 6-7) + xi overlap on warps 0-1
    if (wrp >= 2) {
        const int j = tid - 64;           // gate row (warps 6-7 own n-gate rows 128..191)
        float h_reg = 0.f;
        for (int t = 0; t < HID; t++) {
            if (t == 32) BAR_SYNC(4, 256);
            const ulonglong2* h4 = (const ulonglong2*)&sm[O_HSM];
            u64t a0 = 0ull, a1 = 0ull, a2 = 0ull, a3 = 0ull;
            #pragma unroll
            for (int kk = 0; kk < 8; kk++) {
                ulonglong2 v0 = h4[2*kk], v1 = h4[2*kk+1];
                fma2(a0, wh2[4*kk],   v0.x);
                fma2(a1, wh2[4*kk+1], v0.y);
                fma2(a2, wh2[4*kk+2], v1.x);
                fma2(a3, wh2[4*kk+3], v1.y);
            }
            float gh = bh + red4(a0, a1, a2, a3);
            if (tid < 192) sm[O_GH + j] = gh;   // r/z gates to smem; n-gate stays in reg
            BAR_SYNC(1, 192);
            if (tid >= 192) {
                int e = tid - 192;
                const float* xr = &sm[O_XI + t*XIS];
                float r  = sigmf_(xr[e]      + sm[O_GH + e]);
                float z  = sigmf_(xr[64 + e] + sm[O_GH + 64 + e]);
                float nv = tanhf_(fmaf(r, gh, xr[128 + e]));
                float hn = (1.f - z)*nv + z*h_reg;
                h_reg = hn;
                sm[O_HSM + e]          = hn;
                sm[O_YS + t*YSS + e]   = hn;
            }
            BAR_SYNC(2, 192);
        }
    } else {
        // warps 0-1 (lowest arbiter priority): xi1 chunk1 during steps 0..31
        for (int tile = wrp; tile < 12; tile += 2) {
            int t = 32 + lane;
            xi_tile32(Wi1, bi1, &sm[O_HLNT + t*HLNTS], &sm[O_XI + t*XIS + tile*16], tile*16);
        }
        BAR_SYNC(4, 256);
        // xi2 chunk0 during steps 32..63 (overwrites dead xi1 rows)
        for (int tile = wrp; tile < 12; tile += 2) {
            int t = lane;
            xi_tile64(Wi2, bi2, &sm[O_YS + t*YSS], &sm[O_XI + t*XIS + tile*16], tile*16);
        }
    }
    __syncthreads();

    // ---------------- Phase 10: load Wh2, reset h
    if (wrp >= 2) {
        int j = tid - 64;
        bh = bh2[j];
        const ulonglong2* w = (const ulonglong2*)(Wh2 + j*HID);
        #pragma unroll
        for (int kk = 0; kk < 16; kk++) {
            ulonglong2 t = w[kk];
            wh2[2*kk]   = t.x;
            wh2[2*kk+1] = t.y;
        }
    }
    if (tid < HID) sm[O_HSM + tid] = 0.f;
    __syncthreads();

    // ---------------- Phase 11: GRU2 + xi2 chunk1 overlap on warps 0-1
    if (wrp >= 2) {
        const int j = tid - 64;
        float h_reg = 0.f;
        for (int t = 0; t < HID; t++) {
            if (t == 32) BAR_SYNC(4, 256);
            const ulonglong2* h4 = (const ulonglong2*)&sm[O_HSM];
            u64t a0 = 0ull, a1 = 0ull, a2 = 0ull, a3 = 0ull;
            #pragma unroll
            for (int kk = 0; kk < 8; kk++) {
                ulonglong2 v0 = h4[2*kk], v1 = h4[2*kk+1];
                fma2(a0, wh2[4*kk],   v0.x);
                fma2(a1, wh2[4*kk+1], v0.y);
                fma2(a2, wh2[4*kk+2], v1.x);
                fma2(a3, wh2[4*kk+3], v1.y);
            }
            float gh = bh + red4(a0, a1, a2, a3);
            if (tid < 192) sm[O_GH + j] = gh;
            BAR_SYNC(1, 192);
            if (tid >= 192) {
                int e = tid - 192;
                const float* xr = &sm[O_XI + t*XIS];
                float r  = sigmf_(xr[e]      + sm[O_GH + e]);
                float z  = sigmf_(xr[64 + e] + sm[O_GH + 64 + e]);
                float nv = tanhf_(fmaf(r, gh, xr[128 + e]));
                float hn = (1.f - z)*nv + z*h_reg;
                h_reg = hn;
                sm[O_HSM + e] = hn;
            }
            BAR_SYNC(2, 192);
        }
    } else {
        // warps 0-1: xi2 chunk1 (t=32..63) during GRU2 steps 0..31
        for (int tile = wrp; tile < 12; tile += 2) {
            int t = 32 + lane;
            xi_tile64(Wi2, bi2, &sm[O_YS + t*YSS], &sm[O_XI + t*XIS + tile*16], tile*16);
        }
        BAR_SYNC(4, 256);
    }
    __syncthreads();

    // ---------------- Phase 12: final linear
    if (tid < 9) {
        const ulonglong2* w = (const ulonglong2*)(Wf + tid*HID);
        const ulonglong2* h4 = (const ulonglong2*)&sm[O_HSM];
        u64t a0 = 0ull, a1 = 0ull;
        #pragma unroll
        for (int kk = 0; kk < 16; kk++) {
            ulonglong2 wv = w[kk], hv = h4[kk];
            fma2(a0, wv.x, hv.x);
            fma2(a1, wv.y, hv.y);
        }
        out[b*9 + tid] = bf[tid] + red2(a0, a1);
    }
}

extern "C" void kernel_launch(void* const* d_in, const int* in_sizes, int n_in,
                              void* d_out, int out_size) {
    (void)in_sizes; (void)n_in; (void)out_size;
    const float* x    = (const float*)d_in[0];
    const int*   ei   = (const int*)  d_in[1];
    const float* W1   = (const float*)d_in[2];
    const float* aS1  = (const float*)d_in[3];
    const float* aD1  = (const float*)d_in[4];
    const float* b1   = (const float*)d_in[5];
    const float* W2   = (const float*)d_in[6];
    const float* aS2  = (const float*)d_in[7];
    const float* aD2  = (const float*)d_in[8];
    const float* b2   = (const float*)d_in[9];
    const float* gam  = (const float*)d_in[10];
    const float* bet  = (const float*)d_in[11];
    const float* Wi1  = (const float*)d_in[12];
    const float* Wh1  = (const float*)d_in[13];
    const float* bi1  = (const float*)d_in[14];
    const float* bh1  = (const float*)d_in[15];
    const float* Wi2  = (const float*)d_in[16];
    const float* Wh2  = (const float*)d_in[17];
    const float* bi2  = (const float*)d_in[18];
    const float* bh2  = (const float*)d_in[19];
    const float* Wf   = (const float*)d_in[20];
    const float* bf   = (const float*)d_in[21];
    float* out = (float*)d_out;

    size_t smem = (size_t)SMEM_FLOATS * sizeof(float);
    cudaFuncSetAttribute(fused_gatgru_kernel,
                         cudaFuncAttributeMaxDynamicSharedMemorySize, (int)smem);
    fused_gatgru_kernel<<<512, NTH, smem>>>(
        x, ei, W1, aS1, aD1, b1, W2, aS2, aD2, b2, gam, bet,
        Wi1, Wh1, bi1, bh1, Wi2, Wh2, bi2, bh2, Wf, bf, out);
}

// round 9
// speedup vs baseline: 1.2259x; 1.0286x over previous
#include <cuda_runtime.h>
#include <math.h>

#define NN     32
#define TIN    12
#define HID    64
#define HEADS  8
#define HH     512
#define EPB    256
#define ET     288
#define E_     131072
#define NTH    256
#define RS     68
#define H2S    68
#define HLNTS  36

// ---- kernel A smem map (same as R6) ----
#define O_H1    0
#define O_X     17408
#define O_ES2   17408
#define O_ED2   17440
#define O_M2    17472
#define O_IS2   17504
#define O_AL2   17536
#define O_ES    17792
#define O_E2    17824
#define O_ED    18048
#define O_E     18304
#define O_HLNT  18304
#define O_SRC   20608
#define O_DST   20896
#define O_CNT   21184
#define O_OFF   21216
#define O_SLOT  21249
#define O_CSR   21537
#define O_H2    21828
#define O_G2    24004
#define SMEM_A  26180

// ---- kernel B smem map ----
#define XIS     196
#define YSS     68
#define B_XI    0            // 64*196 = 12544
#define B_YS    12544        // 64*68  = 4352
#define B_H     16896        // 128 (double-buffered h)
#define SMEM_B  17028

typedef unsigned long long u64t;

__device__ float g_xi1[512 * 64 * 192];   // kernel A -> kernel B

__device__ __forceinline__ u64t pk2(float lo, float hi) {
    u64t r; asm("mov.b64 %0, {%1, %2};" : "=l"(r) : "f"(lo), "f"(hi)); return r;
}
__device__ __forceinline__ void fma2(u64t& d, u64t a, u64t b) {
    asm("fma.rn.f32x2 %0, %1, %2, %3;" : "=l"(d) : "l"(a), "l"(b), "l"(d));
}
__device__ __forceinline__ float2 up2(u64t v) {
    float2 f; asm("mov.b64 {%0, %1}, %2;" : "=f"(f.x), "=f"(f.y) : "l"(v)); return f;
}
__device__ __forceinline__ float red2(u64t a, u64t b) {
    float2 fa = up2(a), fb = up2(b);
    return (fa.x + fa.y) + (fb.x + fb.y);
}

__device__ __forceinline__ float sigmf_(float x){ return __fdividef(1.0f, 1.0f + __expf(-x)); }
__device__ __forceinline__ float tanhf_(float x){ return 1.0f - __fdividef(2.0f, __expf(2.0f*x) + 1.0f); }
__device__ __forceinline__ float eluf_(float x){ return x>0.f ? x : (__expf(x) - 1.0f); }
__device__ __forceinline__ float lreluf_(float x){ return x>0.f ? x : 0.2f*x; }

// 16-j slice of xi GEMM (K=32), writes float4s to global
__device__ __forceinline__ void xi_tile32g(const float* __restrict__ W, const float* __restrict__ bias,
                                           const float* src, float* __restrict__ dst, int j0) {
    u64t acc[16];
    #pragma unroll
    for (int q = 0; q < 16; q++) acc[q] = 0ull;
    #pragma unroll
    for (int kc = 0; kc < 32; kc += 4) {
        ulonglong2 hv = *(const ulonglong2*)&src[kc];
        #pragma unroll
        for (int q = 0; q < 16; q++) {
            ulonglong2 wv = *(const ulonglong2*)&W[(j0+q)*32 + kc];
            fma2(acc[q], wv.x, hv.x);
            fma2(acc[q], wv.y, hv.y);
        }
    }
    #pragma unroll
    for (int v = 0; v < 4; v++) {
        float4 o;
        float2 f0 = up2(acc[4*v]),   f1 = up2(acc[4*v+1]);
        float2 f2 = up2(acc[4*v+2]), f3 = up2(acc[4*v+3]);
        o.x = bias[j0+4*v+0] + (f0.x + f0.y);
        o.y = bias[j0+4*v+1] + (f1.x + f1.y);
        o.z = bias[j0+4*v+2] + (f2.x + f2.y);
        o.w = bias[j0+4*v+3] + (f3.x + f3.y);
        *(float4*)&dst[4*v] = o;
    }
}
// 16-j slice of xi GEMM (K=64), writes to smem
__device__ __forceinline__ void xi_tile64(const float* __restrict__ W, const float* __restrict__ bias,
                                          const float* src, float* dst, int j0) {
    u64t acc[16];
    #pragma unroll
    for (int q = 0; q < 16; q++) acc[q] = 0ull;
    #pragma unroll 4
    for (int kc = 0; kc < 64; kc += 4) {
        ulonglong2 hv = *(const ulonglong2*)&src[kc];
        #pragma unroll
        for (int q = 0; q < 16; q++) {
            ulonglong2 wv = *(const ulonglong2*)&W[(j0+q)*64 + kc];
            fma2(acc[q], wv.x, hv.x);
            fma2(acc[q], wv.y, hv.y);
        }
    }
    #pragma unroll
    for (int q = 0; q < 16; q++) {
        float2 f = up2(acc[q]);
        dst[q] = bias[j0+q] + (f.x + f.y);
    }
}

// ================= Kernel A: GAT x2 + LayerNorm + xi1 GEMM =================
__global__ void __launch_bounds__(NTH, 2) gat_kernel(
    const float* __restrict__ x,   const int*   __restrict__ ei,
    const float* __restrict__ W1,  const float* __restrict__ aS1,
    const float* __restrict__ aD1, const float* __restrict__ b1,
    const float* __restrict__ W2,  const float* __restrict__ aS2,
    const float* __restrict__ aD2, const float* __restrict__ b2,
    const float* __restrict__ gamma, const float* __restrict__ beta,
    const float* __restrict__ Wi1, const float* __restrict__ bi1)
{
    extern __shared__ float sm[];
    int* smi = (int*)sm;
    const int tid = threadIdx.x;
    const int b   = blockIdx.x;

    {
        const float4* xg = (const float4*)(x + b*NN*TIN);
        float4* xs = (float4*)&sm[O_X];
        if (tid < 96) xs[tid] = xg[tid];
    }
    for (int k = tid; k < ET; k += NTH) {
        int s, d;
        if (k < EPB) { s = ei[b*EPB + k] - b*NN; d = ei[E_ + b*EPB + k] - b*NN; }
        else         { s = d = k - EPB; }
        smi[O_SRC + k] = s; smi[O_DST + k] = d;
    }
    if (tid < NN) smi[O_CNT + tid] = 0;
    __syncthreads();

    // h1 = x @ W1
    for (int jj = 0; jj < 2; jj++) {
        int j = tid + jj*NTH;
        int h = j >> 6, c = j & 63;
        u64t wp[6];
        #pragma unroll
        for (int k = 0; k < 6; k++)
            wp[k] = pk2(W1[(2*k)*HH + j], W1[(2*k+1)*HH + j]);
        for (int n = 0; n < NN; n++) {
            const u64t* xr = (const u64t*)&sm[O_X + n*TIN];
            u64t a0 = 0ull, a1 = 0ull;
            fma2(a0, xr[0], wp[0]);
            fma2(a1, xr[1], wp[1]);
            fma2(a0, xr[2], wp[2]);
            fma2(a1, xr[3], wp[3]);
            fma2(a0, xr[4], wp[4]);
            fma2(a1, xr[5], wp[5]);
            sm[O_H1 + (n*8 + h)*RS + c] = red2(a0, a1);
        }
    }
    for (int k = tid; k < ET; k += NTH)
        smi[O_SLOT + k] = atomicAdd(&smi[O_CNT + smi[O_DST + k]], 1);
    __syncthreads();

    // es/ed dots + prefix sum
    {
        int n = tid >> 3, h = tid & 7;
        const ulonglong2* hr = (const ulonglong2*)&sm[O_H1 + (n*8 + h)*RS];
        const ulonglong2* as = (const ulonglong2*)(aS1 + h*HID);
        const ulonglong2* ad = (const ulonglong2*)(aD1 + h*HID);
        u64t e0 = 0ull, e1 = 0ull, d0 = 0ull, d1 = 0ull;
        #pragma unroll
        for (int kk = 0; kk < 16; kk++) {
            ulonglong2 v = hr[kk], a = as[kk], g = ad[kk];
            fma2(e0, v.x, a.x);
            fma2(e1, v.y, a.y);
            fma2(d0, v.x, g.x);
            fma2(d1, v.y, g.y);
        }
        sm[O_ES + n*8 + h] = red2(e0, e1);
        sm[O_ED + n*8 + h] = red2(d0, d1);
    }
    if (tid == 0) {
        int acc = 0;
        for (int d = 0; d < NN; d++) { smi[O_OFF + d] = acc; acc += smi[O_CNT + d]; }
        smi[O_OFF + NN] = acc;
    }
    __syncthreads();

    // edge scores + CSR scatter
    for (int k = tid; k < ET; k += NTH) {
        int s = smi[O_SRC + k], d = smi[O_DST + k];
        const float4* es = (const float4*)&sm[O_ES + s*8];
        const float4* ed = (const float4*)&sm[O_ED + d*8];
        float4* eo = (float4*)&sm[O_E + k*8];
        float4 a0 = es[0], a1 = es[1], b0 = ed[0], b1 = ed[1];
        float4 r0, r1;
        r0.x = lreluf_(a0.x + b0.x); r0.y = lreluf_(a0.y + b0.y);
        r0.z = lreluf_(a0.z + b0.z); r0.w = lreluf_(a0.w + b0.w);
        r1.x = lreluf_(a1.x + b1.x); r1.y = lreluf_(a1.y + b1.y);
        r1.z = lreluf_(a1.z + b1.z); r1.w = lreluf_(a1.w + b1.w);
        eo[0] = r0; eo[1] = r1;
    }
    for (int k = tid; k < ET; k += NTH)
        smi[O_CSR + smi[O_OFF + smi[O_DST + k]] + smi[O_SLOT + k]] = k;
    __syncthreads();

    // GAT1 softmax + aggregation
    {
        int dst = tid >> 3, h = tid & 7;
        int o   = smi[O_OFF + dst], deg = smi[O_OFF + dst + 1] - o;
        float m = -1e30f;
        for (int i = 0; i < deg; i++)
            m = fmaxf(m, sm[O_E + smi[O_CSR + o + i]*8 + h]);
        float s = 0.f;
        for (int i = 0; i < deg; i++) {
            int k = smi[O_CSR + o + i];
            float p = __expf(sm[O_E + k*8 + h] - m);
            sm[O_E + k*8 + h] = p;
            s += p;
        }
        float inv = __fdividef(1.f, s + 1e-16f);
        u64t acc[32];
        #pragma unroll
        for (int j = 0; j < 32; j++) acc[j] = 0ull;
        for (int i = 0; i < deg; i++) {
            int k = smi[O_CSR + o + i];
            u64t pp = pk2(sm[O_E + k*8 + h], sm[O_E + k*8 + h]);
            const ulonglong2* hr = (const ulonglong2*)&sm[O_H1 + (smi[O_SRC + k]*8 + h)*RS];
            #pragma unroll
            for (int j = 0; j < 16; j++) {
                ulonglong2 v = hr[j];
                fma2(acc[2*j],   pp, v.x);
                fma2(acc[2*j+1], pp, v.y);
            }
        }
        __syncthreads();
        float4* orow = (float4*)&sm[O_H1 + (dst*8 + h)*RS];
        const float4* bb = (const float4*)(b1 + h*HID);
        #pragma unroll
        for (int j = 0; j < 16; j++) {
            float4 bv = bb[j], r;
            float2 lo = up2(acc[2*j]), hi = up2(acc[2*j+1]);
            r.x = eluf_(fmaf(lo.x, inv, bv.x));
            r.y = eluf_(fmaf(lo.y, inv, bv.y));
            r.z = eluf_(fmaf(hi.x, inv, bv.z));
            r.w = eluf_(fmaf(hi.y, inv, bv.w));
            orow[j] = r;
        }
    }
    __syncthreads();

    // h2 = out1 @ W2
    {
        int c = tid & 63, grp = tid >> 6;
        u64t accA[8], accB[8];
        #pragma unroll
        for (int i = 0; i < 8; i++) { accA[i] = 0ull; accB[i] = 0ull; }
        for (int hd = 0; hd < 8; hd++) {
            const float* w2p = W2 + hd*64*HID + c;
            #pragma unroll 4
            for (int kc = 0; kc < 64; kc += 4) {
                u64t wA = pk2(w2p[(kc+0)*HID], w2p[(kc+1)*HID]);
                u64t wB = pk2(w2p[(kc+2)*HID], w2p[(kc+3)*HID]);
                #pragma unroll
                for (int i = 0; i < 8; i++) {
                    ulonglong2 v = *(const ulonglong2*)&sm[O_H1 + ((grp*8+i)*8 + hd)*RS + kc];
                    fma2(accA[i], v.x, wA);
                    fma2(accB[i], v.y, wB);
                }
            }
        }
        #pragma unroll
        for (int i = 0; i < 8; i++)
            sm[O_H2 + (grp*8+i)*H2S + c] = red2(accA[i], accB[i]);
    }
    __syncthreads();

    // GAT2 attention
    if (tid < 64) {
        int n = tid & 31;
        const ulonglong2* a  = (const ulonglong2*)((tid < 32) ? aS2 : aD2);
        const ulonglong2* hr = (const ulonglong2*)&sm[O_H2 + n*H2S];
        u64t a0 = 0ull, a1 = 0ull;
        #pragma unroll
        for (int kk = 0; kk < 16; kk++) {
            ulonglong2 v = hr[kk], w = a[kk];
            fma2(a0, v.x, w.x);
            fma2(a1, v.y, w.y);
        }
        sm[(tid < 32 ? O_ES2 : O_ED2) + n] = red2(a0, a1);
    }
    __syncthreads();
    for (int k = tid; k < ET; k += NTH)
        sm[O_E2 + k] = lreluf_(sm[O_ES2 + smi[O_SRC + k]] + sm[O_ED2 + smi[O_DST + k]]);
    __syncthreads();
    if (tid < NN) {
        int o = smi[O_OFF + tid], deg = smi[O_OFF + tid + 1] - o;
        float m = -1e30f;
        for (int i = 0; i < deg; i++) m = fmaxf(m, sm[O_E2 + smi[O_CSR + o + i]]);
        float s = 0.f;
        for (int i = 0; i < deg; i++) s += __expf(sm[O_E2 + smi[O_CSR + o + i]] - m);
        sm[O_M2 + tid]  = m;
        sm[O_IS2 + tid] = __fdividef(1.f, s + 1e-16f);
    }
    __syncthreads();
    for (int k = tid; k < ET; k += NTH) {
        int d = smi[O_DST + k];
        sm[O_AL2 + k] = __expf(sm[O_E2 + k] - sm[O_M2 + d]) * sm[O_IS2 + d];
    }
    __syncthreads();
    {
        int dst = tid >> 3, cc = (tid & 7) * 8;
        int o = smi[O_OFF + dst], deg = smi[O_OFF + dst + 1] - o;
        u64t a0 = 0ull, a1 = 0ull, a2 = 0ull, a3 = 0ull;
        for (int i = 0; i < deg; i++) {
            int k = smi[O_CSR + o + i];
            float al = sm[O_AL2 + k];
            u64t pp = pk2(al, al);
            const ulonglong2* hr = (const ulonglong2*)&sm[O_H2 + smi[O_SRC + k]*H2S + cc];
            ulonglong2 v0 = hr[0], v1 = hr[1];
            fma2(a0, pp, v0.x);
            fma2(a1, pp, v0.y);
            fma2(a2, pp, v1.x);
            fma2(a3, pp, v1.y);
        }
        const float4* bb = (const float4*)(b2 + cc);
        float4 b0 = bb[0], b1v = bb[1], r0, r1;
        float2 f0 = up2(a0), f1 = up2(a1), f2 = up2(a2), f3 = up2(a3);
        r0.x = eluf_(f0.x + b0.x); r0.y = eluf_(f0.y + b0.y);
        r0.z = eluf_(f1.x + b0.z); r0.w = eluf_(f1.y + b0.w);
        r1.x = eluf_(f2.x + b1v.x); r1.y = eluf_(f2.y + b1v.y);
        r1.z = eluf_(f3.x + b1v.z); r1.w = eluf_(f3.y + b1v.w);
        float4* g = (float4*)&sm[O_G2 + dst*H2S + cc];
        g[0] = r0; g[1] = r1;
    }
    __syncthreads();

    // LayerNorm + transpose -> hlnT[t][n]
    if (tid < NN) {
        const float4* r4 = (const float4*)&sm[O_G2 + tid*H2S];
        float4 row[16];
        float mu = 0.f;
        #pragma unroll
        for (int kk = 0; kk < 16; kk++) {
            row[kk] = r4[kk];
            mu += (row[kk].x + row[kk].y) + (row[kk].z + row[kk].w);
        }
        mu *= (1.f/HID);
        float var = 0.f;
        #pragma unroll
        for (int kk = 0; kk < 16; kk++) {
            float dx = row[kk].x-mu, dy = row[kk].y-mu, dz = row[kk].z-mu, dw = row[kk].w-mu;
            var += fmaf(dx,dx, dy*dy) + fmaf(dz,dz, dw*dw);
        }
        var *= (1.f/HID);
        float is = rsqrtf(var + 1e-5f);
        #pragma unroll
        for (int kk = 0; kk < 16; kk++) {
            int t = kk*4;
            sm[O_HLNT + (t+0)*HLNTS + tid] = (row[kk].x - mu)*is*gamma[t+0] + beta[t+0];
            sm[O_HLNT + (t+1)*HLNTS + tid] = (row[kk].y - mu)*is*gamma[t+1] + beta[t+1];
            sm[O_HLNT + (t+2)*HLNTS + tid] = (row[kk].z - mu)*is*gamma[t+2] + beta[t+2];
            sm[O_HLNT + (t+3)*HLNTS + tid] = (row[kk].w - mu)*is*gamma[t+3] + beta[t+3];
        }
    }
    __syncthreads();

    // xi1 = hlnT @ Wi1^T + bi1 -> global (24 tiles of 16j x 32t over 8 warps)
    {
        const int wrp = tid >> 5, lane = tid & 31;
        float* gx = g_xi1 + b * (64*192);
        for (int tile = wrp; tile < 24; tile += 8) {
            int j0 = (tile >> 1) * 16;
            int t  = (tile & 1) * 32 + lane;
            xi_tile32g(Wi1, bi1, &sm[O_HLNT + t*HLNTS], gx + t*192 + j0, j0);
        }
    }
}

// ================= Kernel B: GRU1 + xi2 + GRU2 + head =================
__global__ void __launch_bounds__(NTH, 3) gru_kernel(
    const float* __restrict__ Wh1, const float* __restrict__ bh1,
    const float* __restrict__ Wi2, const float* __restrict__ bi2,
    const float* __restrict__ Wh2, const float* __restrict__ bh2,
    const float* __restrict__ Wf,  const float* __restrict__ bf,
    float* __restrict__ out)
{
    extern __shared__ float sm[];
    const int tid = threadIdx.x;
    const int b   = blockIdx.x;
    const int e   = tid >> 2;       // element 0..63
    const int q   = tid & 3;        // quad lane (k-slice q*16..q*16+15)

    // load xi1 from global into smem (stride 196)
    {
        const float4* gx = (const float4*)(g_xi1 + b * (64*192));
        for (int v = tid; v < 3072; v += NTH) {
            int t = v / 48, j4 = v - t*48;
            *(float4*)&sm[B_XI + t*XIS + j4*4] = gx[v];
        }
    }
    if (tid < HID) sm[B_H + tid] = 0.f;   // h buffer 0
    __syncthreads();

    // ---- GRU1 ----
    {
        u64t w[24];
        #pragma unroll
        for (int g = 0; g < 3; g++) {
            const ulonglong2* wr = (const ulonglong2*)(Wh1 + (g*64 + e)*HID + q*16);
            #pragma unroll
            for (int kk = 0; kk < 4; kk++) {
                ulonglong2 t2 = wr[kk];
                w[g*8 + 2*kk]     = t2.x;
                w[g*8 + 2*kk + 1] = t2.y;
            }
        }
        float bhr = bh1[e], bhz = bh1[64 + e], bhn = bh1[128 + e];
        float h_prev = 0.f;
        for (int t = 0; t < HID; t++) {
            const ulonglong2* hb = (const ulonglong2*)&sm[B_H + (t&1)*64 + q*16];
            ulonglong2 h0 = hb[0], h1 = hb[1], h2 = hb[2], h3 = hb[3];
            u64t ar0=0ull, ar1=0ull, az0=0ull, az1=0ull, an0=0ull, an1=0ull;
            fma2(ar0, w[0], h0.x); fma2(ar1, w[1], h0.y);
            fma2(ar0, w[2], h1.x); fma2(ar1, w[3], h1.y);
            fma2(ar0, w[4], h2.x); fma2(ar1, w[5], h2.y);
            fma2(ar0, w[6], h3.x); fma2(ar1, w[7], h3.y);
            fma2(az0, w[8],  h0.x); fma2(az1, w[9],  h0.y);
            fma2(az0, w[10], h1.x); fma2(az1, w[11], h1.y);
            fma2(az0, w[12], h2.x); fma2(az1, w[13], h2.y);
            fma2(az0, w[14], h3.x); fma2(az1, w[15], h3.y);
            fma2(an0, w[16], h0.x); fma2(an1, w[17], h0.y);
            fma2(an0, w[18], h1.x); fma2(an1, w[19], h1.y);
            fma2(an0, w[20], h2.x); fma2(an1, w[21], h2.y);
            fma2(an0, w[22], h3.x); fma2(an1, w[23], h3.y);
            float gr = red2(ar0, ar1), gz = red2(az0, az1), gn = red2(an0, an1);
            gr += __shfl_xor_sync(0xffffffffu, gr, 1);
            gz += __shfl_xor_sync(0xffffffffu, gz, 1);
            gn += __shfl_xor_sync(0xffffffffu, gn, 1);
            gr += __shfl_xor_sync(0xffffffffu, gr, 2);
            gz += __shfl_xor_sync(0xffffffffu, gz, 2);
            gn += __shfl_xor_sync(0xffffffffu, gn, 2);
            const float* xr = &sm[B_XI + t*XIS];
            float r  = sigmf_(xr[e]       + gr + bhr);
            float z  = sigmf_(xr[64 + e]  + gz + bhz);
            float nv = tanhf_(fmaf(r, gn + bhn, xr[128 + e]));
            float hn = (1.f - z)*nv + z*h_prev;
            h_prev = hn;
            if (q == 0) {
                sm[B_H + ((t+1)&1)*64 + e] = hn;
                sm[B_YS + t*YSS + e]       = hn;
            }
            __syncthreads();
        }
    }

    // ---- xi2 = ys @ Wi2^T + bi2 (warp-tiled) ----
    {
        const int wrp = tid >> 5, lane = tid & 31;
        for (int tile = wrp; tile < 24; tile += 8) {
            int j0 = (tile >> 1) * 16;
            int t  = (tile & 1) * 32 + lane;
            xi_tile64(Wi2, bi2, &sm[B_YS + t*YSS], &sm[B_XI + t*XIS + j0], j0);
        }
    }
    if (tid < HID) sm[B_H + tid] = 0.f;
    __syncthreads();

    // ---- GRU2 (final h only) ----
    {
        u64t w[24];
        #pragma unroll
        for (int g = 0; g < 3; g++) {
            const ulonglong2* wr = (const ulonglong2*)(Wh2 + (g*64 + e)*HID + q*16);
            #pragma unroll
            for (int kk = 0; kk < 4; kk++) {
                ulonglong2 t2 = wr[kk];
                w[g*8 + 2*kk]     = t2.x;
                w[g*8 + 2*kk + 1] = t2.y;
            }
        }
        float bhr = bh2[e], bhz = bh2[64 + e], bhn = bh2[128 + e];
        float h_prev = 0.f;
        for (int t = 0; t < HID; t++) {
            const ulonglong2* hb = (const ulonglong2*)&sm[B_H + (t&1)*64 + q*16];
            ulonglong2 h0 = hb[0], h1 = hb[1], h2 = hb[2], h3 = hb[3];
            u64t ar0=0ull, ar1=0ull, az0=0ull, az1=0ull, an0=0ull, an1=0ull;
            fma2(ar0, w[0], h0.x); fma2(ar1, w[1], h0.y);
            fma2(ar0, w[2], h1.x); fma2(ar1, w[3], h1.y);
            fma2(ar0, w[4], h2.x); fma2(ar1, w[5], h2.y);
            fma2(ar0, w[6], h3.x); fma2(ar1, w[7], h3.y);
            fma2(az0, w[8],  h0.x); fma2(az1, w[9],  h0.y);
            fma2(az0, w[10], h1.x); fma2(az1, w[11], h1.y);
            fma2(az0, w[12], h2.x); fma2(az1, w[13], h2.y);
            fma2(az0, w[14], h3.x); fma2(az1, w[15], h3.y);
            fma2(an0, w[16], h0.x); fma2(an1, w[17], h0.y);
            fma2(an0, w[18], h1.x); fma2(an1, w[19], h1.y);
            fma2(an0, w[20], h2.x); fma2(an1, w[21], h2.y);
            fma2(an0, w[22], h3.x); fma2(an1, w[23], h3.y);
            float gr = red2(ar0, ar1), gz = red2(az0, az1), gn = red2(an0, an1);
            gr += __shfl_xor_sync(0xffffffffu, gr, 1);
            gz += __shfl_xor_sync(0xffffffffu, gz, 1);
            gn += __shfl_xor_sync(0xffffffffu, gn, 1);
            gr += __shfl_xor_sync(0xffffffffu, gr, 2);
            gz += __shfl_xor_sync(0xffffffffu, gz, 2);
            gn += __shfl_xor_sync(0xffffffffu, gn, 2);
            const float* xr = &sm[B_XI + t*XIS];
            float r  = sigmf_(xr[e]       + gr + bhr);
            float z  = sigmf_(xr[64 + e]  + gz + bhz);
            float nv = tanhf_(fmaf(r, gn + bhn, xr[128 + e]));
            float hn = (1.f - z)*nv + z*h_prev;
            h_prev = hn;
            if (q == 0)
                sm[B_H + ((t+1)&1)*64 + e] = hn;
            __syncthreads();
        }
    }

    // final linear: h_last is in buffer 0 (after t=63, stored at (64)&1 = 0)
    if (tid < 9) {
        const ulonglong2* w = (const ulonglong2*)(Wf + tid*HID);
        const ulonglong2* h4 = (const ulonglong2*)&sm[B_H];
        u64t a0 = 0ull, a1 = 0ull;
        #pragma unroll
        for (int kk = 0; kk < 16; kk++) {
            ulonglong2 wv = w[kk], hv = h4[kk];
            fma2(a0, wv.x, hv.x);
            fma2(a1, wv.y, hv.y);
        }
        out[b*9 + tid] = bf[tid] + red2(a0, a1);
    }
}

extern "C" void kernel_launch(void* const* d_in, const int* in_sizes, int n_in,
                              void* d_out, int out_size) {
    (void)in_sizes; (void)n_in; (void)out_size;
    const float* x    = (const float*)d_in[0];
    const int*   ei   = (const int*)  d_in[1];
    const float* W1   = (const float*)d_in[2];
    const float* aS1  = (const float*)d_in[3];
    const float* aD1  = (const float*)d_in[4];
    const float* b1   = (const float*)d_in[5];
    const float* W2   = (const float*)d_in[6];
    const float* aS2  = (const float*)d_in[7];
    const float* aD2  = (const float*)d_in[8];
    const float* b2   = (const float*)d_in[9];
    const float* gam  = (const float*)d_in[10];
    const float* bet  = (const float*)d_in[11];
    const float* Wi1  = (const float*)d_in[12];
    const float* Wh1  = (const float*)d_in[13];
    const float* bi1  = (const float*)d_in[14];
    const float* bh1  = (const float*)d_in[15];
    const float* Wi2  = (const float*)d_in[16];
    const float* Wh2  = (const float*)d_in[17];
    const float* bi2  = (const float*)d_in[18];
    const float* bh2  = (const float*)d_in[19];
    const float* Wf   = (const float*)d_in[20];
    const float* bf   = (const float*)d_in[21];
    float* out = (float*)d_out;

    size_t smemA = (size_t)SMEM_A * sizeof(float);
    size_t smemB = (size_t)SMEM_B * sizeof(float);
    cudaFuncSetAttribute(gat_kernel, cudaFuncAttributeMaxDynamicSharedMemorySize, (int)smemA);
    cudaFuncSetAttribute(gru_kernel, cudaFuncAttributeMaxDynamicSharedMemorySize, (int)smemB);
    gat_kernel<<<512, NTH, smemA>>>(x, ei, W1, aS1, aD1, b1, W2, aS2, aD2, b2,
                                    gam, bet, Wi1, bi1);
    gru_kernel<<<512, NTH, smemB>>>(Wh1, bh1, Wi2, bi2, Wh2, bh2, Wf, bf, out);
}

// round 11
// speedup vs baseline: 1.4061x; 1.1471x over previous
#include <cuda_runtime.h>
#include <math.h>

#define NN     32
#define TIN    12
#define HID    64
#define HEADS  8
#define HH     512
#define EPB    256
#define ET     288
#define E_     131072
#define NTH    256
#define RS     68
#define H2S    68
#define HLNTS  36
#define XIS    196
#define YSS    68

#define O_H1    0
#define O_XI    0
#define O_YS    12544
#define O_X     17408
#define O_ES2   17408
#define O_ED2   17440
#define O_M2    17472
#define O_IS2   17504
#define O_AL2   17536
#define O_ES    17792
#define O_E2    17824
#define O_ED    18048
#define O_E     18304
#define O_HLNT  18304
#define O_SRC   20608
#define O_DST   20896
#define O_CNT   21184
#define O_OFF   21216
#define O_SLOT  21249
#define O_CSR   21537
#define O_H2    21828
#define O_G2    24004
#define O_HB    24004    // 128 floats: double-buffered GRU hidden state
#define SMEM_FLOATS 26180

typedef unsigned long long u64t;

__device__ __forceinline__ u64t pk2(float lo, float hi) {
    u64t r; asm("mov.b64 %0, {%1, %2};" : "=l"(r) : "f"(lo), "f"(hi)); return r;
}
__device__ __forceinline__ void fma2(u64t& d, u64t a, u64t b) {
    asm("fma.rn.f32x2 %0, %1, %2, %3;" : "=l"(d) : "l"(a), "l"(b), "l"(d));
}
__device__ __forceinline__ float2 up2(u64t v) {
    float2 f; asm("mov.b64 {%0, %1}, %2;" : "=f"(f.x), "=f"(f.y) : "l"(v)); return f;
}
__device__ __forceinline__ float red2(u64t a, u64t b) {
    float2 fa = up2(a), fb = up2(b);
    return (fa.x + fa.y) + (fb.x + fb.y);
}

__device__ __forceinline__ float sigmf_(float x){ return __fdividef(1.0f, 1.0f + __expf(-x)); }
__device__ __forceinline__ float tanhf_(float x){ return 1.0f - __fdividef(2.0f, __expf(2.0f*x) + 1.0f); }
__device__ __forceinline__ float eluf_(float x){ return x>0.f ? x : (__expf(x) - 1.0f); }
__device__ __forceinline__ float lreluf_(float x){ return x>0.f ? x : 0.2f*x; }

__device__ __forceinline__ void xi_tile32(const float* __restrict__ W, const float* __restrict__ bias,
                                          const float* src, float* dst, int j0) {
    u64t acc[16];
    #pragma unroll
    for (int q = 0; q < 16; q++) acc[q] = 0ull;
    #pragma unroll
    for (int kc = 0; kc < 32; kc += 4) {
        ulonglong2 hv = *(const ulonglong2*)&src[kc];
        #pragma unroll
        for (int q = 0; q < 16; q++) {
            ulonglong2 wv = *(const ulonglong2*)&W[(j0+q)*32 + kc];
            fma2(acc[q], wv.x, hv.x);
            fma2(acc[q], wv.y, hv.y);
        }
    }
    #pragma unroll
    for (int q = 0; q < 16; q++) {
        float2 f = up2(acc[q]);
        dst[q] = bias[j0+q] + (f.x + f.y);
    }
}
__device__ __forceinline__ void xi_tile64(const float* __restrict__ W, const float* __restrict__ bias,
                                          const float* src, float* dst, int j0) {
    u64t acc[16];
    #pragma unroll
    for (int q = 0; q < 16; q++) acc[q] = 0ull;
    #pragma unroll 4
    for (int kc = 0; kc < 64; kc += 4) {
        ulonglong2 hv = *(const ulonglong2*)&src[kc];
        #pragma unroll
        for (int q = 0; q < 16; q++) {
            ulonglong2 wv = *(const ulonglong2*)&W[(j0+q)*64 + kc];
            fma2(acc[q], wv.x, hv.x);
            fma2(acc[q], wv.y, hv.y);
        }
    }
    #pragma unroll
    for (int q = 0; q < 16; q++) {
        float2 f = up2(acc[q]);
        dst[q] = bias[j0+q] + (f.x + f.y);
    }
}

__global__ void __launch_bounds__(NTH, 2) fused_gatgru_kernel(
    const float* __restrict__ x,   const int*   __restrict__ ei,
    const float* __restrict__ W1,  const float* __restrict__ aS1,
    const float* __restrict__ aD1, const float* __restrict__ b1,
    const float* __restrict__ W2,  const float* __restrict__ aS2,
    const float* __restrict__ aD2, const float* __restrict__ b2,
    const float* __restrict__ gamma, const float* __restrict__ beta,
    const float* __restrict__ Wi1, const float* __restrict__ Wh1,
    const float* __restrict__ bi1, const float* __restrict__ bh1,
    const float* __restrict__ Wi2, const float* __restrict__ Wh2,
    const float* __restrict__ bi2, const float* __restrict__ bh2,
    const float* __restrict__ Wf,  const float* __restrict__ bf,
    float* __restrict__ out)
{
    extern __shared__ float sm[];
    int* smi = (int*)sm;
    const int tid = threadIdx.x;
    const int b   = blockIdx.x;

    // ---------------- Phase 0
    {
        const float4* xg = (const float4*)(x + b*NN*TIN);
        float4* xs = (float4*)&sm[O_X];
        if (tid < 96) xs[tid] = xg[tid];
    }
    for (int k = tid; k < ET; k += NTH) {
        int s, d;
        if (k < EPB) { s = ei[b*EPB + k] - b*NN; d = ei[E_ + b*EPB + k] - b*NN; }
        else         { s = d = k - EPB; }
        smi[O_SRC + k] = s; smi[O_DST + k] = d;
    }
    if (tid < NN) smi[O_CNT + tid] = 0;
    __syncthreads();

    // ---------------- Phase 1: h1 = x @ W1
    for (int jj = 0; jj < 2; jj++) {
        int j = tid + jj*NTH;
        int h = j >> 6, c = j & 63;
        u64t wp[6];
        #pragma unroll
        for (int k = 0; k < 6; k++)
            wp[k] = pk2(W1[(2*k)*HH + j], W1[(2*k+1)*HH + j]);
        for (int n = 0; n < NN; n++) {
            const u64t* xr = (const u64t*)&sm[O_X + n*TIN];
            u64t a0 = 0ull, a1 = 0ull;
            fma2(a0, xr[0], wp[0]);
            fma2(a1, xr[1], wp[1]);
            fma2(a0, xr[2], wp[2]);
            fma2(a1, xr[3], wp[3]);
            fma2(a0, xr[4], wp[4]);
            fma2(a1, xr[5], wp[5]);
            sm[O_H1 + (n*8 + h)*RS + c] = red2(a0, a1);
        }
    }
    for (int k = tid; k < ET; k += NTH)
        smi[O_SLOT + k] = atomicAdd(&smi[O_CNT + smi[O_DST + k]], 1);
    __syncthreads();

    // ---------------- Phase 2: es/ed dots + prefix sum
    {
        int n = tid >> 3, h = tid & 7;
        const ulonglong2* hr = (const ulonglong2*)&sm[O_H1 + (n*8 + h)*RS];
        const ulonglong2* as = (const ulonglong2*)(aS1 + h*HID);
        const ulonglong2* ad = (const ulonglong2*)(aD1 + h*HID);
        u64t e0 = 0ull, e1 = 0ull, d0 = 0ull, d1 = 0ull;
        #pragma unroll
        for (int kk = 0; kk < 16; kk++) {
            ulonglong2 v = hr[kk], a = as[kk], g = ad[kk];
            fma2(e0, v.x, a.x);
            fma2(e1, v.y, a.y);
            fma2(d0, v.x, g.x);
            fma2(d1, v.y, g.y);
        }
        sm[O_ES + n*8 + h] = red2(e0, e1);
        sm[O_ED + n*8 + h] = red2(d0, d1);
    }
    if (tid == 0) {
        int acc = 0;
        for (int d = 0; d < NN; d++) { smi[O_OFF + d] = acc; acc += smi[O_CNT + d]; }
        smi[O_OFF + NN] = acc;
    }
    __syncthreads();

    // ---------------- Phase 3: edge scores + CSR scatter
    for (int k = tid; k < ET; k += NTH) {
        int s = smi[O_SRC + k], d = smi[O_DST + k];
        const float4* es = (const float4*)&sm[O_ES + s*8];
        const float4* ed = (const float4*)&sm[O_ED + d*8];
        float4* eo = (float4*)&sm[O_E + k*8];
        float4 a0 = es[0], a1 = es[1], b0 = ed[0], b1 = ed[1];
        float4 r0, r1;
        r0.x = lreluf_(a0.x + b0.x); r0.y = lreluf_(a0.y + b0.y);
        r0.z = lreluf_(a0.z + b0.z); r0.w = lreluf_(a0.w + b0.w);
        r1.x = lreluf_(a1.x + b1.x); r1.y = lreluf_(a1.y + b1.y);
        r1.z = lreluf_(a1.z + b1.z); r1.w = lreluf_(a1.w + b1.w);
        eo[0] = r0; eo[1] = r1;
    }
    for (int k = tid; k < ET; k += NTH)
        smi[O_CSR + smi[O_OFF + smi[O_DST + k]] + smi[O_SLOT + k]] = k;
    __syncthreads();

    // ---------------- Phase 4: GAT1 softmax + aggregation
    {
        int dst = tid >> 3, h = tid & 7;
        int o   = smi[O_OFF + dst], deg = smi[O_OFF + dst + 1] - o;
        float m = -1e30f;
        for (int i = 0; i < deg; i++)
            m = fmaxf(m, sm[O_E + smi[O_CSR + o + i]*8 + h]);
        float s = 0.f;
        for (int i = 0; i < deg; i++) {
            int k = smi[O_CSR + o + i];
            float p = __expf(sm[O_E + k*8 + h] - m);
            sm[O_E + k*8 + h] = p;
            s += p;
        }
        float inv = __fdividef(1.f, s + 1e-16f);
        u64t acc[32];
        #pragma unroll
        for (int j = 0; j < 32; j++) acc[j] = 0ull;
        for (int i = 0; i < deg; i++) {
            int k = smi[O_CSR + o + i];
            u64t pp = pk2(sm[O_E + k*8 + h], sm[O_E + k*8 + h]);
            const ulonglong2* hr = (const ulonglong2*)&sm[O_H1 + (smi[O_SRC + k]*8 + h)*RS];
            #pragma unroll
            for (int j = 0; j < 16; j++) {
                ulonglong2 v = hr[j];
                fma2(acc[2*j],   pp, v.x);
                fma2(acc[2*j+1], pp, v.y);
            }
        }
        __syncthreads();
        float4* orow = (float4*)&sm[O_H1 + (dst*8 + h)*RS];
        const float4* bb = (const float4*)(b1 + h*HID);
        #pragma unroll
        for (int j = 0; j < 16; j++) {
            float4 bv = bb[j], r;
            float2 lo = up2(acc[2*j]), hi = up2(acc[2*j+1]);
            r.x = eluf_(fmaf(lo.x, inv, bv.x));
            r.y = eluf_(fmaf(lo.y, inv, bv.y));
            r.z = eluf_(fmaf(hi.x, inv, bv.z));
            r.w = eluf_(fmaf(hi.y, inv, bv.w));
            orow[j] = r;
        }
    }
    __syncthreads();

    // ---------------- Phase 5: h2 = out1 @ W2
    {
        int c = tid & 63, grp = tid >> 6;
        u64t accA[8], accB[8];
        #pragma unroll
        for (int i = 0; i < 8; i++) { accA[i] = 0ull; accB[i] = 0ull; }
        for (int hd = 0; hd < 8; hd++) {
            const float* w2p = W2 + hd*64*HID + c;
            #pragma unroll 4
            for (int kc = 0; kc < 64; kc += 4) {
                u64t wA = pk2(w2p[(kc+0)*HID], w2p[(kc+1)*HID]);
                u64t wB = pk2(w2p[(kc+2)*HID], w2p[(kc+3)*HID]);
                #pragma unroll
                for (int i = 0; i < 8; i++) {
                    ulonglong2 v = *(const ulonglong2*)&sm[O_H1 + ((grp*8+i)*8 + hd)*RS + kc];
                    fma2(accA[i], v.x, wA);
                    fma2(accB[i], v.y, wB);
                }
            }
        }
        #pragma unroll
        for (int i = 0; i < 8; i++)
            sm[O_H2 + (grp*8+i)*H2S + c] = red2(accA[i], accB[i]);
    }
    __syncthreads();

    // ---------------- Phase 6: GAT2 attention
    if (tid < 64) {
        int n = tid & 31;
        const ulonglong2* a  = (const ulonglong2*)((tid < 32) ? aS2 : aD2);
        const ulonglong2* hr = (const ulonglong2*)&sm[O_H2 + n*H2S];
        u64t a0 = 0ull, a1 = 0ull;
        #pragma unroll
        for (int kk = 0; kk < 16; kk++) {
            ulonglong2 v = hr[kk], w = a[kk];
            fma2(a0, v.x, w.x);
            fma2(a1, v.y, w.y);
        }
        sm[(tid < 32 ? O_ES2 : O_ED2) + n] = red2(a0, a1);
    }
    __syncthreads();
    for (int k = tid; k < ET; k += NTH)
        sm[O_E2 + k] = lreluf_(sm[O_ES2 + smi[O_SRC + k]] + sm[O_ED2 + smi[O_DST + k]]);
    __syncthreads();
    if (tid < NN) {
        int o = smi[O_OFF + tid], deg = smi[O_OFF + tid + 1] - o;
        float m = -1e30f;
        for (int i = 0; i < deg; i++) m = fmaxf(m, sm[O_E2 + smi[O_CSR + o + i]]);
        float s = 0.f;
        for (int i = 0; i < deg; i++) s += __expf(sm[O_E2 + smi[O_CSR + o + i]] - m);
        sm[O_M2 + tid]  = m;
        sm[O_IS2 + tid] = __fdividef(1.f, s + 1e-16f);
    }
    __syncthreads();
    for (int k = tid; k < ET; k += NTH) {
        int d = smi[O_DST + k];
        sm[O_AL2 + k] = __expf(sm[O_E2 + k] - sm[O_M2 + d]) * sm[O_IS2 + d];
    }
    __syncthreads();
    {
        int dst = tid >> 3, cc = (tid & 7) * 8;
        int o = smi[O_OFF + dst], deg = smi[O_OFF + dst + 1] - o;
        u64t a0 = 0ull, a1 = 0ull, a2 = 0ull, a3 = 0ull;
        for (int i = 0; i < deg; i++) {
            int k = smi[O_CSR + o + i];
            float al = sm[O_AL2 + k];
            u64t pp = pk2(al, al);
            const ulonglong2* hr = (const ulonglong2*)&sm[O_H2 + smi[O_SRC + k]*H2S + cc];
            ulonglong2 v0 = hr[0], v1 = hr[1];
            fma2(a0, pp, v0.x);
            fma2(a1, pp, v0.y);
            fma2(a2, pp, v1.x);
            fma2(a3, pp, v1.y);
        }
        const float4* bb = (const float4*)(b2 + cc);
        float4 b0 = bb[0], b1v = bb[1], r0, r1;
        float2 f0 = up2(a0), f1 = up2(a1), f2 = up2(a2), f3 = up2(a3);
        r0.x = eluf_(f0.x + b0.x); r0.y = eluf_(f0.y + b0.y);
        r0.z = eluf_(f1.x + b0.z); r0.w = eluf_(f1.y + b0.w);
        r1.x = eluf_(f2.x + b1v.x); r1.y = eluf_(f2.y + b1v.y);
        r1.z = eluf_(f3.x + b1v.z); r1.w = eluf_(f3.y + b1v.w);
        float4* g = (float4*)&sm[O_G2 + dst*H2S + cc];
        g[0] = r0; g[1] = r1;
    }
    __syncthreads();

    // ---------------- Phase 7: LayerNorm + transpose -> hlnT[t][n]
    if (tid < NN) {
        const float4* r4 = (const float4*)&sm[O_G2 + tid*H2S];
        float4 row[16];
        float mu = 0.f;
        #pragma unroll
        for (int kk = 0; kk < 16; kk++) {
            row[kk] = r4[kk];
            mu += (row[kk].x + row[kk].y) + (row[kk].z + row[kk].w);
        }
        mu *= (1.f/HID);
        float var = 0.f;
        #pragma unroll
        for (int kk = 0; kk < 16; kk++) {
            float dx = row[kk].x-mu, dy = row[kk].y-mu, dz = row[kk].z-mu, dw = row[kk].w-mu;
            var += fmaf(dx,dx, dy*dy) + fmaf(dz,dz, dw*dw);
        }
        var *= (1.f/HID);
        float is = rsqrtf(var + 1e-5f);
        #pragma unroll
        for (int kk = 0; kk < 16; kk++) {
            int t = kk*4;
            sm[O_HLNT + (t+0)*HLNTS + tid] = (row[kk].x - mu)*is*gamma[t+0] + beta[t+0];
            sm[O_HLNT + (t+1)*HLNTS + tid] = (row[kk].y - mu)*is*gamma[t+1] + beta[t+1];
            sm[O_HLNT + (t+2)*HLNTS + tid] = (row[kk].z - mu)*is*gamma[t+2] + beta[t+2];
            sm[O_HLNT + (t+3)*HLNTS + tid] = (row[kk].w - mu)*is*gamma[t+3] + beta[t+3];
        }
    }
    __syncthreads();

    const int wrp  = tid >> 5;
    const int lane = tid & 31;

    // ---------------- Phase 8: xi1 = hlnT @ Wi1^T + bi1 (all 8 warps, 24 tiles)
    for (int tile = wrp; tile < 24; tile += 8) {
        int j0 = (tile >> 1) * 16;
        int t  = (tile & 1) * 32 + lane;
        xi_tile32(Wi1, bi1, &sm[O_HLNT + t*HLNTS], &sm[O_XI + t*XIS + j0], j0);
    }

    // GRU thread layout: e = tid>>2 (element 0..63), q = tid&3 (16-k slice)
    const int e = tid >> 2, q = tid & 3;
    u64t w[24]; float bhr, bhz, bhn;
    {
        bhr = bh1[e]; bhz = bh1[64 + e]; bhn = bh1[128 + e];
        #pragma unroll
        for (int g = 0; g < 3; g++) {
            const ulonglong2* wr = (const ulonglong2*)(Wh1 + (g*64 + e)*HID + q*16);
            #pragma unroll
            for (int kk = 0; kk < 4; kk++) {
                ulonglong2 t2 = wr[kk];
                w[g*8 + 2*kk]     = t2.x;
                w[g*8 + 2*kk + 1] = t2.y;
            }
        }
    }
    if (tid < HID) sm[O_HB + tid] = 0.f;   // h buffer 0
    __syncthreads();

    // ---------------- Phase 9: GRU1 (4 thr/elem, all 256 threads, 1 barrier/step)
    {
        float h_prev = 0.f;
        for (int t = 0; t < HID; t++) {
            const ulonglong2* hb = (const ulonglong2*)&sm[O_HB + (t&1)*64 + q*16];
            ulonglong2 h0 = hb[0], h1 = hb[1], h2 = hb[2], h3 = hb[3];
            u64t ar0=0ull, ar1=0ull, az0=0ull, az1=0ull, an0=0ull, an1=0ull;
            fma2(ar0, w[0], h0.x); fma2(ar1, w[1], h0.y);
            fma2(ar0, w[2], h1.x); fma2(ar1, w[3], h1.y);
            fma2(ar0, w[4], h2.x); fma2(ar1, w[5], h2.y);
            fma2(ar0, w[6], h3.x); fma2(ar1, w[7], h3.y);
            fma2(az0, w[8],  h0.x); fma2(az1, w[9],  h0.y);
            fma2(az0, w[10], h1.x); fma2(az1, w[11], h1.y);
            fma2(az0, w[12], h2.x); fma2(az1, w[13], h2.y);
            fma2(az0, w[14], h3.x); fma2(az1, w[15], h3.y);
            fma2(an0, w[16], h0.x); fma2(an1, w[17], h0.y);
            fma2(an0, w[18], h1.x); fma2(an1, w[19], h1.y);
            fma2(an0, w[20], h2.x); fma2(an1, w[21], h2.y);
            fma2(an0, w[22], h3.x); fma2(an1, w[23], h3.y);
            float gr = red2(ar0, ar1), gz = red2(az0, az1), gn = red2(an0, an1);
            gr += __shfl_xor_sync(0xffffffffu, gr, 1);
            gz += __shfl_xor_sync(0xffffffffu, gz, 1);
            gn += __shfl_xor_sync(0xffffffffu, gn, 1);
            gr += __shfl_xor_sync(0xffffffffu, gr, 2);
            gz += __shfl_xor_sync(0xffffffffu, gz, 2);
            gn += __shfl_xor_sync(0xffffffffu, gn, 2);
            const float* xr = &sm[O_XI + t*XIS];
            float r  = sigmf_(xr[e]       + gr + bhr);
            float z  = sigmf_(xr[64 + e]  + gz + bhz);
            float nv = tanhf_(fmaf(r, gn + bhn, xr[128 + e]));
            float hn = (1.f - z)*nv + z*h_prev;
            h_prev = hn;
            if (q == 0)      sm[O_HB + ((t+1)&1)*64 + e] = hn;
            else if (q == 1) sm[O_YS + t*YSS + e]        = hn;
            __syncthreads();
        }
    }

    // ---------------- Phase 10: xi2 = ys @ Wi2^T + bi2 (all 8 warps)
    for (int tile = wrp; tile < 24; tile += 8) {
        int j0 = (tile >> 1) * 16;
        int t  = (tile & 1) * 32 + lane;
        xi_tile64(Wi2, bi2, &sm[O_YS + t*YSS], &sm[O_XI + t*XIS + j0], j0);
    }
    {
        bhr = bh2[e]; bhz = bh2[64 + e]; bhn = bh2[128 + e];
        #pragma unroll
        for (int g = 0; g < 3; g++) {
            const ulonglong2* wr = (const ulonglong2*)(Wh2 + (g*64 + e)*HID + q*16);
            #pragma unroll
            for (int kk = 0; kk < 4; kk++) {
                ulonglong2 t2 = wr[kk];
                w[g*8 + 2*kk]     = t2.x;
                w[g*8 + 2*kk + 1] = t2.y;
            }
        }
    }
    if (tid < HID) sm[O_HB + tid] = 0.f;
    __syncthreads();

    // ---------------- Phase 11: GRU2 (final h only)
    {
        float h_prev = 0.f;
        for (int t = 0; t < HID; t++) {
            const ulonglong2* hb = (const ulonglong2*)&sm[O_HB + (t&1)*64 + q*16];
            ulonglong2 h0 = hb[0], h1 = hb[1], h2 = hb[2], h3 = hb[3];
            u64t ar0=0ull, ar1=0ull, az0=0ull, az1=0ull, an0=0ull, an1=0ull;
            fma2(ar0, w[0], h0.x); fma2(ar1, w[1], h0.y);
            fma2(ar0, w[2], h1.x); fma2(ar1, w[3], h1.y);
            fma2(ar0, w[4], h2.x); fma2(ar1, w[5], h2.y);
            fma2(ar0, w[6], h3.x); fma2(ar1, w[7], h3.y);
            fma2(az0, w[8],  h0.x); fma2(az1, w[9],  h0.y);
            fma2(az0, w[10], h1.x); fma2(az1, w[11], h1.y);
            fma2(az0, w[12], h2.x); fma2(az1, w[13], h2.y);
            fma2(az0, w[14], h3.x); fma2(az1, w[15], h3.y);
            fma2(an0, w[16], h0.x); fma2(an1, w[17], h0.y);
            fma2(an0, w[18], h1.x); fma2(an1, w[19], h1.y);
            fma2(an0, w[20], h2.x); fma2(an1, w[21], h2.y);
            fma2(an0, w[22], h3.x); fma2(an1, w[23], h3.y);
            float gr = red2(ar0, ar1), gz = red2(az0, az1), gn = red2(an0, an1);
            gr += __shfl_xor_sync(0xffffffffu, gr, 1);
            gz += __shfl_xor_sync(0xffffffffu, gz, 1);
            gn += __shfl_xor_sync(0xffffffffu, gn, 1);
            gr += __shfl_xor_sync(0xffffffffu, gr, 2);
            gz += __shfl_xor_sync(0xffffffffu, gz, 2);
            gn += __shfl_xor_sync(0xffffffffu, gn, 2);
            const float* xr = &sm[O_XI + t*XIS];
            float r  = sigmf_(xr[e]       + gr + bhr);
            float z  = sigmf_(xr[64 + e]  + gz + bhz);
            float nv = tanhf_(fmaf(r, gn + bhn, xr[128 + e]));
            float hn = (1.f - z)*nv + z*h_prev;
            h_prev = hn;
            if (q == 0) sm[O_HB + ((t+1)&1)*64 + e] = hn;
            __syncthreads();
        }
    }

    // ---------------- Phase 12: final linear (h_last in buffer 0)
    if (tid < 9) {
        const ulonglong2* wv4 = (const ulonglong2*)(Wf + tid*HID);
        const ulonglong2* h4  = (const ulonglong2*)&sm[O_HB];
        u64t a0 = 0ull, a1 = 0ull;
        #pragma unroll
        for (int kk = 0; kk < 16; kk++) {
            ulonglong2 wv = wv4[kk], hv = h4[kk];
            fma2(a0, wv.x, hv.x);
            fma2(a1, wv.y, hv.y);
        }
        out[b*9 + tid] = bf[tid] + red2(a0, a1);
    }
}

extern "C" void kernel_launch(void* const* d_in, const int* in_sizes, int n_in,
                              void* d_out, int out_size) {
    (void)in_sizes; (void)n_in; (void)out_size;
    const float* x    = (const float*)d_in[0];
    const int*   ei   = (const int*)  d_in[1];
    const float* W1   = (const float*)d_in[2];
    const float* aS1  = (const float*)d_in[3];
    const float* aD1  = (const float*)d_in[4];
    const float* b1   = (const float*)d_in[5];
    const float* W2   = (const float*)d_in[6];
    const float* aS2  = (const float*)d_in[7];
    const float* aD2  = (const float*)d_in[8];
    const float* b2   = (const float*)d_in[9];
    const float* gam  = (const float*)d_in[10];
    const float* bet  = (const float*)d_in[11];
    const float* Wi1  = (const float*)d_in[12];
    const float* Wh1  = (const float*)d_in[13];
    const float* bi1  = (const float*)d_in[14];
    const float* bh1  = (const float*)d_in[15];
    const float* Wi2  = (const float*)d_in[16];
    const float* Wh2  = (const float*)d_in[17];
    const float* bi2  = (const float*)d_in[18];
    const float* bh2  = (const float*)d_in[19];
    const float* Wf   = (const float*)d_in[20];
    const float* bf   = (const float*)d_in[21];
    float* out = (float*)d_out;

    size_t smem = (size_t)SMEM_FLOATS * sizeof(float);
    cudaFuncSetAttribute(fused_gatgru_kernel,
                         cudaFuncAttributeMaxDynamicSharedMemorySize, (int)smem);
    fused_gatgru_kernel<<<512, NTH, smem>>>(
        x, ei, W1, aS1, aD1, b1, W2, aS2, aD2, b2, gam, bet,
        Wi1, Wh1, bi1, bh1, Wi2, Wh2, bi2, bh2, Wf, bf, out);
}

// round 12
// speedup vs baseline: 1.4328x; 1.0190x over previous
#include <cuda_runtime.h>
#include <math.h>

#define NN     32
#define TIN    12
#define HID    64
#define HEADS  8
#define HH     512
#define EPB    256
#define ET     288
#define E_     131072
#define NTH    256
#define RS     68
#define H2S    68
#define HLNTS  36
#define XIS    196
#define YSS    68

#define O_H1    0
#define O_XI    0
#define O_YS    12544
#define O_X     17408
#define O_ES2   17408
#define O_ED2   17440
#define O_M2    17472
#define O_IS2   17504
#define O_AL2   17536
#define O_ES    17792
#define O_E2    17824
#define O_ED    18048
#define O_E     18304
#define O_HLNT  18304
#define O_SRC   20608
#define O_DST   20896
#define O_CNT   21184
#define O_OFF   21216
#define O_SLOT  21249
#define O_CSR   21537
#define O_H2    21828
#define O_G2    24004
#define O_HSM   24004
#define O_GH    24068
#define SMEM_FLOATS 26180

typedef unsigned long long u64t;

#define BAR_SYNC(id, n)   asm volatile("bar.sync %0, %1;"   :: "n"(id), "n"(n) : "memory")
#define BAR_ARRIVE(id, n) asm volatile("bar.arrive %0, %1;" :: "n"(id), "n"(n) : "memory")

// packed weight pair buffers (constants, filled by prologue kernel each launch)
__device__ u64t g_w2p[256 * 64];   // pair p of W2 column c at [p*64 + c]
__device__ u64t g_w1p[6 * 512];    // pair p of W1 column j at [p*512 + j]

__device__ __forceinline__ u64t pk2(float lo, float hi) {
    u64t r; asm("mov.b64 %0, {%1, %2};" : "=l"(r) : "f"(lo), "f"(hi)); return r;
}
__device__ __forceinline__ void fma2(u64t& d, u64t a, u64t b) {
    asm("fma.rn.f32x2 %0, %1, %2, %3;" : "=l"(d) : "l"(a), "l"(b), "l"(d));
}
__device__ __forceinline__ float2 up2(u64t v) {
    float2 f; asm("mov.b64 {%0, %1}, %2;" : "=f"(f.x), "=f"(f.y) : "l"(v)); return f;
}
__device__ __forceinline__ float red2(u64t a, u64t b) {
    float2 fa = up2(a), fb = up2(b);
    return (fa.x + fa.y) + (fb.x + fb.y);
}
__device__ __forceinline__ float red4(u64t a, u64t b, u64t c, u64t d) {
    float2 fa = up2(a), fb = up2(b), fc = up2(c), fd = up2(d);
    return ((fa.x + fa.y) + (fb.x + fb.y)) + ((fc.x + fc.y) + (fd.x + fd.y));
}

__device__ __forceinline__ float sigmf_(float x){ return __fdividef(1.0f, 1.0f + __expf(-x)); }
__device__ __forceinline__ float tanhf_(float x){ return 1.0f - __fdividef(2.0f, __expf(2.0f*x) + 1.0f); }
__device__ __forceinline__ float eluf_(float x){ return x>0.f ? x : (__expf(x) - 1.0f); }
__device__ __forceinline__ float lreluf_(float x){ return x>0.f ? x : 0.2f*x; }

__device__ __forceinline__ void xi_tile32(const float* __restrict__ W, const float* __restrict__ bias,
                                          const float* src, float* dst, int j0) {
    u64t acc[16];
    #pragma unroll
    for (int q = 0; q < 16; q++) acc[q] = 0ull;
    #pragma unroll
    for (int kc = 0; kc < 32; kc += 4) {
        ulonglong2 hv = *(const ulonglong2*)&src[kc];
        #pragma unroll
        for (int q = 0; q < 16; q++) {
            ulonglong2 wv = *(const ulonglong2*)&W[(j0+q)*32 + kc];
            fma2(acc[q], wv.x, hv.x);
            fma2(acc[q], wv.y, hv.y);
        }
    }
    #pragma unroll
    for (int q = 0; q < 16; q++) {
        float2 f = up2(acc[q]);
        dst[q] = bias[j0+q] + (f.x + f.y);
    }
}
__device__ __forceinline__ void xi_tile64(const float* __restrict__ W, const float* __restrict__ bias,
                                          const float* src, float* dst, int j0) {
    u64t acc[16];
    #pragma unroll
    for (int q = 0; q < 16; q++) acc[q] = 0ull;
    #pragma unroll 4
    for (int kc = 0; kc < 64; kc += 4) {
        ulonglong2 hv = *(const ulonglong2*)&src[kc];
        #pragma unroll
        for (int q = 0; q < 16; q++) {
            ulonglong2 wv = *(const ulonglong2*)&W[(j0+q)*64 + kc];
            fma2(acc[q], wv.x, hv.x);
            fma2(acc[q], wv.y, hv.y);
        }
    }
    #pragma unroll
    for (int q = 0; q < 16; q++) {
        float2 f = up2(acc[q]);
        dst[q] = bias[j0+q] + (f.x + f.y);
    }
}

// prologue: pack W2 (512x64) and W1 (12x512) into f32x2 pairs along k
__global__ void pack_weights_kernel(const float* __restrict__ W1,
                                    const float* __restrict__ W2)
{
    int i = blockIdx.x * 256 + threadIdx.x;
    if (i < 256 * 64) {
        int p = i >> 6, c = i & 63;
        g_w2p[i] = pk2(W2[(2*p)*HID + c], W2[(2*p+1)*HID + c]);
    }
    if (i < 6 * 512) {
        int p = i >> 9, j = i & 511;
        g_w1p[i] = pk2(W1[(2*p)*HH + j], W1[(2*p+1)*HH + j]);
    }
}

__global__ void __launch_bounds__(NTH, 2) fused_gatgru_kernel(
    const float* __restrict__ x,   const int*   __restrict__ ei,
    const float* __restrict__ W1,  const float* __restrict__ aS1,
    const float* __restrict__ aD1, const float* __restrict__ b1,
    const float* __restrict__ W2,  const float* __restrict__ aS2,
    const float* __restrict__ aD2, const float* __restrict__ b2,
    const float* __restrict__ gamma, const float* __restrict__ beta,
    const float* __restrict__ Wi1, const float* __restrict__ Wh1,
    const float* __restrict__ bi1, const float* __restrict__ bh1,
    const float* __restrict__ Wi2, const float* __restrict__ Wh2,
    const float* __restrict__ bi2, const float* __restrict__ bh2,
    const float* __restrict__ Wf,  const float* __restrict__ bf,
    float* __restrict__ out)
{
    extern __shared__ float sm[];
    int* smi = (int*)sm;
    const int tid = threadIdx.x;
    const int b   = blockIdx.x;

    // ---------------- Phase 0
    {
        const float4* xg = (const float4*)(x + b*NN*TIN);
        float4* xs = (float4*)&sm[O_X];
        if (tid < 96) xs[tid] = xg[tid];
    }
    for (int k = tid; k < ET; k += NTH) {
        int s, d;
        if (k < EPB) { s = ei[b*EPB + k] - b*NN; d = ei[E_ + b*EPB + k] - b*NN; }
        else         { s = d = k - EPB; }
        smi[O_SRC + k] = s; smi[O_DST + k] = d;
    }
    if (tid < NN) smi[O_CNT + tid] = 0;
    __syncthreads();

    // ---------------- Phase 1: h1 = x @ W1 (packed weights from g_w1p)
    for (int jj = 0; jj < 2; jj++) {
        int j = tid + jj*NTH;
        int h = j >> 6, c = j & 63;
        u64t wp[6];
        #pragma unroll
        for (int k = 0; k < 6; k++)
            wp[k] = g_w1p[k*HH + j];
        for (int n = 0; n < NN; n++) {
            const u64t* xr = (const u64t*)&sm[O_X + n*TIN];
            u64t a0 = 0ull, a1 = 0ull;
            fma2(a0, xr[0], wp[0]);
            fma2(a1, xr[1], wp[1]);
            fma2(a0, xr[2], wp[2]);
            fma2(a1, xr[3], wp[3]);
            fma2(a0, xr[4], wp[4]);
            fma2(a1, xr[5], wp[5]);
            sm[O_H1 + (n*8 + h)*RS + c] = red2(a0, a1);
        }
    }
    for (int k = tid; k < ET; k += NTH)
        smi[O_SLOT + k] = atomicAdd(&smi[O_CNT + smi[O_DST + k]], 1);
    __syncthreads();

    // ---------------- Phase 2: es/ed dots + prefix sum
    {
        int n = tid >> 3, h = tid & 7;
        const ulonglong2* hr = (const ulonglong2*)&sm[O_H1 + (n*8 + h)*RS];
        const ulonglong2* as = (const ulonglong2*)(aS1 + h*HID);
        const ulonglong2* ad = (const ulonglong2*)(aD1 + h*HID);
        u64t e0 = 0ull, e1 = 0ull, d0 = 0ull, d1 = 0ull;
        #pragma unroll
        for (int kk = 0; kk < 16; kk++) {
            ulonglong2 v = hr[kk], a = as[kk], g = ad[kk];
            fma2(e0, v.x, a.x);
            fma2(e1, v.y, a.y);
            fma2(d0, v.x, g.x);
            fma2(d1, v.y, g.y);
        }
        sm[O_ES + n*8 + h] = red2(e0, e1);
        sm[O_ED + n*8 + h] = red2(d0, d1);
    }
    if (tid == 0) {
        int acc = 0;
        for (int d = 0; d < NN; d++) { smi[O_OFF + d] = acc; acc += smi[O_CNT + d]; }
        smi[O_OFF + NN] = acc;
    }
    __syncthreads();

    // ---------------- Phase 3: edge scores + CSR scatter
    for (int k = tid; k < ET; k += NTH) {
        int s = smi[O_SRC + k], d = smi[O_DST + k];
        const float4* es = (const float4*)&sm[O_ES + s*8];
        const float4* ed = (const float4*)&sm[O_ED + d*8];
        float4* eo = (float4*)&sm[O_E + k*8];
        float4 a0 = es[0], a1 = es[1], b0 = ed[0], b1 = ed[1];
        float4 r0, r1;
        r0.x = lreluf_(a0.x + b0.x); r0.y = lreluf_(a0.y + b0.y);
        r0.z = lreluf_(a0.z + b0.z); r0.w = lreluf_(a0.w + b0.w);
        r1.x = lreluf_(a1.x + b1.x); r1.y = lreluf_(a1.y + b1.y);
        r1.z = lreluf_(a1.z + b1.z); r1.w = lreluf_(a1.w + b1.w);
        eo[0] = r0; eo[1] = r1;
    }
    for (int k = tid; k < ET; k += NTH)
        smi[O_CSR + smi[O_OFF + smi[O_DST + k]] + smi[O_SLOT + k]] = k;
    __syncthreads();

    // ---------------- Phase 4: GAT1 softmax + aggregation
    {
        int dst = tid >> 3, h = tid & 7;
        int o   = smi[O_OFF + dst], deg = smi[O_OFF + dst + 1] - o;
        float m = -1e30f;
        for (int i = 0; i < deg; i++)
            m = fmaxf(m, sm[O_E + smi[O_CSR + o + i]*8 + h]);
        float s = 0.f;
        for (int i = 0; i < deg; i++) {
            int k = smi[O_CSR + o + i];
            float p = __expf(sm[O_E + k*8 + h] - m);
            sm[O_E + k*8 + h] = p;
            s += p;
        }
        float inv = __fdividef(1.f, s + 1e-16f);
        u64t acc[32];
        #pragma unroll
        for (int j = 0; j < 32; j++) acc[j] = 0ull;
        for (int i = 0; i < deg; i++) {
            int k = smi[O_CSR + o + i];
            u64t pp = pk2(sm[O_E + k*8 + h], sm[O_E + k*8 + h]);
            const ulonglong2* hr = (const ulonglong2*)&sm[O_H1 + (smi[O_SRC + k]*8 + h)*RS];
            #pragma unroll
            for (int j = 0; j < 16; j++) {
                ulonglong2 v = hr[j];
                fma2(acc[2*j],   pp, v.x);
                fma2(acc[2*j+1], pp, v.y);
            }
        }
        __syncthreads();
        float4* orow = (float4*)&sm[O_H1 + (dst*8 + h)*RS];
        const float4* bb = (const float4*)(b1 + h*HID);
        #pragma unroll
        for (int j = 0; j < 16; j++) {
            float4 bv = bb[j], r;
            float2 lo = up2(acc[2*j]), hi = up2(acc[2*j+1]);
            r.x = eluf_(fmaf(lo.x, inv, bv.x));
            r.y = eluf_(fmaf(lo.y, inv, bv.y));
            r.z = eluf_(fmaf(hi.x, inv, bv.z));
            r.w = eluf_(fmaf(hi.y, inv, bv.w));
            orow[j] = r;
        }
    }
    __syncthreads();

    // ---------------- Phase 5: h2 = out1 @ W2 (packed weights from g_w2p, LDG.64)
    {
        int c = tid & 63, grp = tid >> 6;
        u64t accA[8], accB[8];
        #pragma unroll
        for (int i = 0; i < 8; i++) { accA[i] = 0ull; accB[i] = 0ull; }
        for (int hd = 0; hd < 8; hd++) {
            const u64t* w2p = g_w2p + hd*32*64 + c;   // pair index stride 64
            #pragma unroll 4
            for (int kc = 0; kc < 64; kc += 4) {
                u64t wA = w2p[(kc >> 1)*64];
                u64t wB = w2p[((kc >> 1) + 1)*64];
                #pragma unroll
                for (int i = 0; i < 8; i++) {
                    ulonglong2 v = *(const ulonglong2*)&sm[O_H1 + ((grp*8+i)*8 + hd)*RS + kc];
                    fma2(accA[i], v.x, wA);
                    fma2(accB[i], v.y, wB);
                }
            }
        }
        #pragma unroll
        for (int i = 0; i < 8; i++)
            sm[O_H2 + (grp*8+i)*H2S + c] = red2(accA[i], accB[i]);
    }
    __syncthreads();

    // ---------------- Phase 6: GAT2 attention
    if (tid < 64) {
        int n = tid & 31;
        const ulonglong2* a  = (const ulonglong2*)((tid < 32) ? aS2 : aD2);
        const ulonglong2* hr = (const ulonglong2*)&sm[O_H2 + n*H2S];
        u64t a0 = 0ull, a1 = 0ull;
        #pragma unroll
        for (int kk = 0; kk < 16; kk++) {
            ulonglong2 v = hr[kk], w = a[kk];
            fma2(a0, v.x, w.x);
            fma2(a1, v.y, w.y);
        }
        sm[(tid < 32 ? O_ES2 : O_ED2) + n] = red2(a0, a1);
    }
    __syncthreads();
    for (int k = tid; k < ET; k += NTH)
        sm[O_E2 + k] = lreluf_(sm[O_ES2 + smi[O_SRC + k]] + sm[O_ED2 + smi[O_DST + k]]);
    __syncthreads();
    if (tid < NN) {
        int o = smi[O_OFF + tid], deg = smi[O_OFF + tid + 1] - o;
        float m = -1e30f;
        for (int i = 0; i < deg; i++) m = fmaxf(m, sm[O_E2 + smi[O_CSR + o + i]]);
        float s = 0.f;
        for (int i = 0; i < deg; i++) s += __expf(sm[O_E2 + smi[O_CSR + o + i]] - m);
        sm[O_M2 + tid]  = m;
        sm[O_IS2 + tid] = __fdividef(1.f, s + 1e-16f);
    }
    __syncthreads();
    for (int k = tid; k < ET; k += NTH) {
        int d = smi[O_DST + k];
        sm[O_AL2 + k] = __expf(sm[O_E2 + k] - sm[O_M2 + d]) * sm[O_IS2 + d];
    }
    __syncthreads();
    {
        int dst = tid >> 3, cc = (tid & 7) * 8;
        int o = smi[O_OFF + dst], deg = smi[O_OFF + dst + 1] - o;
        u64t a0 = 0ull, a1 = 0ull, a2 = 0ull, a3 = 0ull;
        for (int i = 0; i < deg; i++) {
            int k = smi[O_CSR + o + i];
            float al = sm[O_AL2 + k];
            u64t pp = pk2(al, al);
            const ulonglong2* hr = (const ulonglong2*)&sm[O_H2 + smi[O_SRC + k]*H2S + cc];
            ulonglong2 v0 = hr[0], v1 = hr[1];
            fma2(a0, pp, v0.x);
            fma2(a1, pp, v0.y);
            fma2(a2, pp, v1.x);
            fma2(a3, pp, v1.y);
        }
        const float4* bb = (const float4*)(b2 + cc);
        float4 b0 = bb[0], b1v = bb[1], r0, r1;
        float2 f0 = up2(a0), f1 = up2(a1), f2 = up2(a2), f3 = up2(a3);
        r0.x = eluf_(f0.x + b0.x); r0.y = eluf_(f0.y + b0.y);
        r0.z = eluf_(f1.x + b0.z); r0.w = eluf_(f1.y + b0.w);
        r1.x = eluf_(f2.x + b1v.x); r1.y = eluf_(f2.y + b1v.y);
        r1.z = eluf_(f3.x + b1v.z); r1.w = eluf_(f3.y + b1v.w);
        float4* g = (float4*)&sm[O_G2 + dst*H2S + cc];
        g[0] = r0; g[1] = r1;
    }
    __syncthreads();

    // ---------------- Phase 7: LayerNorm + transpose -> hlnT[t][n]
    if (tid < NN) {
        const float4* r4 = (const float4*)&sm[O_G2 + tid*H2S];
        float4 row[16];
        float mu = 0.f;
        #pragma unroll
        for (int kk = 0; kk < 16; kk++) {
            row[kk] = r4[kk];
            mu += (row[kk].x + row[kk].y) + (row[kk].z + row[kk].w);
        }
        mu *= (1.f/HID);
        float var = 0.f;
        #pragma unroll
        for (int kk = 0; kk < 16; kk++) {
            float dx = row[kk].x-mu, dy = row[kk].y-mu, dz = row[kk].z-mu, dw = row[kk].w-mu;
            var += fmaf(dx,dx, dy*dy) + fmaf(dz,dz, dw*dw);
        }
        var *= (1.f/HID);
        float is = rsqrtf(var + 1e-5f);
        #pragma unroll
        for (int kk = 0; kk < 16; kk++) {
            int t = kk*4;
            sm[O_HLNT + (t+0)*HLNTS + tid] = (row[kk].x - mu)*is*gamma[t+0] + beta[t+0];
            sm[O_HLNT + (t+1)*HLNTS + tid] = (row[kk].y - mu)*is*gamma[t+1] + beta[t+1];
            sm[O_HLNT + (t+2)*HLNTS + tid] = (row[kk].z - mu)*is*gamma[t+2] + beta[t+2];
            sm[O_HLNT + (t+3)*HLNTS + tid] = (row[kk].w - mu)*is*gamma[t+3] + beta[t+3];
        }
    }
    __syncthreads();

    const int wrp  = tid >> 5;
    const int lane = tid & 31;

    // ---------------- Phase 8: xi1 = hlnT @ Wi1^T + bi1 (all 8 warps, 24 tiles)
    for (int tile = wrp; tile < 24; tile += 8) {
        int j0 = (tile >> 1) * 16;
        int t  = (tile & 1) * 32 + lane;
        xi_tile32(Wi1, bi1, &sm[O_HLNT + t*HLNTS], &sm[O_XI + t*XIS + j0], j0);
    }
    // Wh1 rows into registers (threads 0..191; act role = warps 0-1)
    u64t wh2[32]; float bh = 0.f;
    if (tid < 192) {
        bh = bh1[tid];
        const ulonglong2* w = (const ulonglong2*)(Wh1 + tid*HID);
        #pragma unroll
        for (int kk = 0; kk < 16; kk++) {
            ulonglong2 t = w[kk];
            wh2[2*kk]   = t.x;
            wh2[2*kk+1] = t.y;
        }
    }
    if (tid < HID) sm[O_HSM + tid] = 0.f;
    __syncthreads();

    // ---------------- Phase 9: GRU1 recurrence (64 steps), store ys  (R6 engine)
    for (int t = 0; t < HID; t++) {
        if (tid < 192) {
            const ulonglong2* h4 = (const ulonglong2*)&sm[O_HSM];
            u64t a0 = 0ull, a1 = 0ull, a2 = 0ull, a3 = 0ull;
            #pragma unroll
            for (int kk = 0; kk < 8; kk++) {
                ulonglong2 v0 = h4[2*kk], v1 = h4[2*kk+1];
                fma2(a0, wh2[4*kk],   v0.x);
                fma2(a1, wh2[4*kk+1], v0.y);
                fma2(a2, wh2[4*kk+2], v1.x);
                fma2(a3, wh2[4*kk+3], v1.y);
            }
            sm[O_GH + tid] = bh + red4(a0, a1, a2, a3);
        }
        __syncthreads();
        if (tid < HID) {
            const float* xr = &sm[O_XI + t*XIS];
            float r  = sigmf_(xr[tid]       + sm[O_GH + tid]);
            float z  = sigmf_(xr[64 + tid]  + sm[O_GH + 64 + tid]);
            float nv = tanhf_(fmaf(r, sm[O_GH + 128 + tid], xr[128 + tid]));
            float hn = (1.f - z)*nv + z*sm[O_HSM + tid];
            sm[O_HSM + tid]        = hn;
            sm[O_YS + t*YSS + tid] = hn;
        }
        __syncthreads();
    }

    // ---------------- Phase 10: xi2 = ys @ Wi2^T + bi2 (all 8 warps)
    for (int tile = wrp; tile < 24; tile += 8) {
        int j0 = (tile >> 1) * 16;
        int t  = (tile & 1) * 32 + lane;
        xi_tile64(Wi2, bi2, &sm[O_YS + t*YSS], &sm[O_XI + t*XIS + j0], j0);
    }
    if (tid < 192) {
        bh = bh2[tid];
        const ulonglong2* w = (const ulonglong2*)(Wh2 + tid*HID);
        #pragma unroll
        for (int kk = 0; kk < 16; kk++) {
            ulonglong2 t = w[kk];
            wh2[2*kk]   = t.x;
            wh2[2*kk+1] = t.y;
        }
    }
    if (tid < HID) sm[O_HSM + tid] = 0.f;
    __syncthreads();

    // ---------------- Phase 11: GRU2 recurrence (final h only)
    for (int t = 0; t < HID; t++) {
        if (tid < 192) {
            const ulonglong2* h4 = (const ulonglong2*)&sm[O_HSM];
            u64t a0 = 0ull, a1 = 0ull, a2 = 0ull, a3 = 0ull;
            #pragma unroll
            for (int kk = 0; kk < 8; kk++) {
                ulonglong2 v0 = h4[2*kk], v1 = h4[2*kk+1];
                fma2(a0, wh2[4*kk],   v0.x);
                fma2(a1, wh2[4*kk+1], v0.y);
                fma2(a2, wh2[4*kk+2], v1.x);
                fma2(a3, wh2[4*kk+3], v1.y);
            }
            sm[O_GH + tid] = bh + red4(a0, a1, a2, a3);
        }
        __syncthreads();
        if (tid < HID) {
            const float* xr = &sm[O_XI + t*XIS];
            float r  = sigmf_(xr[tid]       + sm[O_GH + tid]);
            float z  = sigmf_(xr[64 + tid]  + sm[O_GH + 64 + tid]);
            float nv = tanhf_(fmaf(r, sm[O_GH + 128 + tid], xr[128 + tid]));
            sm[O_HSM + tid] = (1.f - z)*nv + z*sm[O_HSM + tid];
        }
        __syncthreads();
    }

    // ---------------- Phase 12: final linear
    if (tid < 9) {
        const ulonglong2* w = (const ulonglong2*)(Wf + tid*HID);
        const ulonglong2* h4 = (const ulonglong2*)&sm[O_HSM];
        u64t a0 = 0ull, a1 = 0ull;
        #pragma unroll
        for (int kk = 0; kk < 16; kk++) {
            ulonglong2 wv = w[kk], hv = h4[kk];
            fma2(a0, wv.x, hv.x);
            fma2(a1, wv.y, hv.y);
        }
        out[b*9 + tid] = bf[tid] + red2(a0, a1);
    }
}

extern "C" void kernel_launch(void* const* d_in, const int* in_sizes, int n_in,
                              void* d_out, int out_size) {
    (void)in_sizes; (void)n_in; (void)out_size;
    const float* x    = (const float*)d_in[0];
    const int*   ei   = (const int*)  d_in[1];
    const float* W1   = (const float*)d_in[2];
    const float* aS1  = (const float*)d_in[3];
    const float* aD1  = (const float*)d_in[4];
    const float* b1   = (const float*)d_in[5];
    const float* W2   = (const float*)d_in[6];
    const float* aS2  = (const float*)d_in[7];
    const float* aD2  = (const float*)d_in[8];
    const float* b2   = (const float*)d_in[9];
    const float* gam  = (const float*)d_in[10];
    const float* bet  = (const float*)d_in[11];
    const float* Wi1  = (const float*)d_in[12];
    const float* Wh1  = (const float*)d_in[13];
    const float* bi1  = (const float*)d_in[14];
    const float* bh1  = (const float*)d_in[15];
    const float* Wi2  = (const float*)d_in[16];
    const float* Wh2  = (const float*)d_in[17];
    const float* bi2  = (const float*)d_in[18];
    const float* bh2  = (const float*)d_in[19];
    const float* Wf   = (const float*)d_in[20];
    const float* bf   = (const float*)d_in[21];
    float* out = (float*)d_out;

    size_t smem = (size_t)SMEM_FLOATS * sizeof(float);
    cudaFuncSetAttribute(fused_gatgru_kernel,
                         cudaFuncAttributeMaxDynamicSharedMemorySize, (int)smem);
    pack_weights_kernel<<<64, 256>>>(W1, W2);
    fused_gatgru_kernel<<<512, NTH, smem>>>(
        x, ei, W1, aS1, aD1, b1, W2, aS2, aD2, b2, gam, bet,
        Wi1, Wh1, bi1, bh1, Wi2, Wh2, bi2, bh2, Wf, bf, out);
}

// round 13
// speedup vs baseline: 1.4752x; 1.0296x over previous
#include <cuda_runtime.h>
#include <math.h>

#define NN     32
#define TIN    12
#define HID    64
#define HEADS  8
#define HH     512
#define EPB    256
#define ET     288
#define E_     131072
#define NTH    256
#define RS     68
#define H2S    68
#define HLNTS  36
#define XIS    196
#define YSS    68

#define O_H1    0
#define O_XI    0
#define O_YS    12544
#define O_X     17408
#define O_ES2   17408
#define O_ED2   17440
#define O_M2    17472
#define O_IS2   17504
#define O_AL2   17536
#define O_ES    17792
#define O_E2    17824
#define O_ED    18048
#define O_E     18304
#define O_HLNT  18304
#define O_SRC   20608
#define O_DST   20896
#define O_CNT   21184
#define O_OFF   21216
#define O_SLOT  21249
#define O_CSR   21537
#define O_H2    21828
#define O_G2    24004
#define O_HSM   24004
#define O_GH    24068
#define SMEM_FLOATS 26180

typedef unsigned long long u64t;

#define BAR_SYNC(id, n) asm volatile("bar.sync %0, %1;" :: "n"(id), "n"(n) : "memory")

// packed weight pair buffers (constants, filled by prologue kernel each launch)
__device__ u64t g_w2p[256 * 64];   // pair p of W2 column c at [p*64 + c]
__device__ u64t g_w1p[6 * 512];    // pair p of W1 column j at [p*512 + j]

__device__ __forceinline__ u64t pk2(float lo, float hi) {
    u64t r; asm("mov.b64 %0, {%1, %2};" : "=l"(r) : "f"(lo), "f"(hi)); return r;
}
__device__ __forceinline__ void fma2(u64t& d, u64t a, u64t b) {
    asm("fma.rn.f32x2 %0, %1, %2, %3;" : "=l"(d) : "l"(a), "l"(b), "l"(d));
}
__device__ __forceinline__ float2 up2(u64t v) {
    float2 f; asm("mov.b64 {%0, %1}, %2;" : "=f"(f.x), "=f"(f.y) : "l"(v)); return f;
}
__device__ __forceinline__ float red2(u64t a, u64t b) {
    float2 fa = up2(a), fb = up2(b);
    return (fa.x + fa.y) + (fb.x + fb.y);
}
__device__ __forceinline__ float red4(u64t a, u64t b, u64t c, u64t d) {
    float2 fa = up2(a), fb = up2(b), fc = up2(c), fd = up2(d);
    return ((fa.x + fa.y) + (fb.x + fb.y)) + ((fc.x + fc.y) + (fd.x + fd.y));
}

__device__ __forceinline__ float sigmf_(float x){ return __fdividef(1.0f, 1.0f + __expf(-x)); }
__device__ __forceinline__ float tanhf_(float x){ return 1.0f - __fdividef(2.0f, __expf(2.0f*x) + 1.0f); }
__device__ __forceinline__ float eluf_(float x){ return x>0.f ? x : (__expf(x) - 1.0f); }
__device__ __forceinline__ float lreluf_(float x){ return x>0.f ? x : 0.2f*x; }

__device__ __forceinline__ void xi_tile32(const float* __restrict__ W, const float* __restrict__ bias,
                                          const float* src, float* dst, int j0) {
    u64t acc[16];
    #pragma unroll
    for (int q = 0; q < 16; q++) acc[q] = 0ull;
    #pragma unroll
    for (int kc = 0; kc < 32; kc += 4) {
        ulonglong2 hv = *(const ulonglong2*)&src[kc];
        #pragma unroll
        for (int q = 0; q < 16; q++) {
            ulonglong2 wv = *(const ulonglong2*)&W[(j0+q)*32 + kc];
            fma2(acc[q], wv.x, hv.x);
            fma2(acc[q], wv.y, hv.y);
        }
    }
    #pragma unroll
    for (int q = 0; q < 16; q++) {
        float2 f = up2(acc[q]);
        dst[q] = bias[j0+q] + (f.x + f.y);
    }
}
__device__ __forceinline__ void xi_tile64(const float* __restrict__ W, const float* __restrict__ bias,
                                          const float* src, float* dst, int j0) {
    u64t acc[16];
    #pragma unroll
    for (int q = 0; q < 16; q++) acc[q] = 0ull;
    #pragma unroll 4
    for (int kc = 0; kc < 64; kc += 4) {
        ulonglong2 hv = *(const ulonglong2*)&src[kc];
        #pragma unroll
        for (int q = 0; q < 16; q++) {
            ulonglong2 wv = *(const ulonglong2*)&W[(j0+q)*64 + kc];
            fma2(acc[q], wv.x, hv.x);
            fma2(acc[q], wv.y, hv.y);
        }
    }
    #pragma unroll
    for (int q = 0; q < 16; q++) {
        float2 f = up2(acc[q]);
        dst[q] = bias[j0+q] + (f.x + f.y);
    }
}

// prologue: pack W2 (512x64) and W1 (12x512) into f32x2 pairs along k
__global__ void pack_weights_kernel(const float* __restrict__ W1,
                                    const float* __restrict__ W2)
{
    int i = blockIdx.x * 256 + threadIdx.x;
    if (i < 256 * 64) {
        int p = i >> 6, c = i & 63;
        g_w2p[i] = pk2(W2[(2*p)*HID + c], W2[(2*p+1)*HID + c]);
    }
    if (i < 6 * 512) {
        int p = i >> 9, j = i & 511;
        g_w1p[i] = pk2(W1[(2*p)*HH + j], W1[(2*p+1)*HH + j]);
    }
}

__global__ void __launch_bounds__(NTH, 2) fused_gatgru_kernel(
    const float* __restrict__ x,   const int*   __restrict__ ei,
    const float* __restrict__ W1,  const float* __restrict__ aS1,
    const float* __restrict__ aD1, const float* __restrict__ b1,
    const float* __restrict__ W2,  const float* __restrict__ aS2,
    const float* __restrict__ aD2, const float* __restrict__ b2,
    const float* __restrict__ gamma, const float* __restrict__ beta,
    const float* __restrict__ Wi1, const float* __restrict__ Wh1,
    const float* __restrict__ bi1, const float* __restrict__ bh1,
    const float* __restrict__ Wi2, const float* __restrict__ Wh2,
    const float* __restrict__ bi2, const float* __restrict__ bh2,
    const float* __restrict__ Wf,  const float* __restrict__ bf,
    float* __restrict__ out)
{
    extern __shared__ float sm[];
    int* smi = (int*)sm;
    const int tid = threadIdx.x;
    const int b   = blockIdx.x;

    // ---------------- Phase 0
    {
        const float4* xg = (const float4*)(x + b*NN*TIN);
        float4* xs = (float4*)&sm[O_X];
        if (tid < 96) xs[tid] = xg[tid];
    }
    for (int k = tid; k < ET; k += NTH) {
        int s, d;
        if (k < EPB) { s = ei[b*EPB + k] - b*NN; d = ei[E_ + b*EPB + k] - b*NN; }
        else         { s = d = k - EPB; }
        smi[O_SRC + k] = s; smi[O_DST + k] = d;
    }
    if (tid < NN) smi[O_CNT + tid] = 0;
    __syncthreads();

    // ---------------- Phase 1: h1 = x @ W1 (packed weights from g_w1p)
    for (int jj = 0; jj < 2; jj++) {
        int j = tid + jj*NTH;
        int h = j >> 6, c = j & 63;
        u64t wp[6];
        #pragma unroll
        for (int k = 0; k < 6; k++)
            wp[k] = g_w1p[k*HH + j];
        for (int n = 0; n < NN; n++) {
            const u64t* xr = (const u64t*)&sm[O_X + n*TIN];
            u64t a0 = 0ull, a1 = 0ull;
            fma2(a0, xr[0], wp[0]);
            fma2(a1, xr[1], wp[1]);
            fma2(a0, xr[2], wp[2]);
            fma2(a1, xr[3], wp[3]);
            fma2(a0, xr[4], wp[4]);
            fma2(a1, xr[5], wp[5]);
            sm[O_H1 + (n*8 + h)*RS + c] = red2(a0, a1);
        }
    }
    for (int k = tid; k < ET; k += NTH)
        smi[O_SLOT + k] = atomicAdd(&smi[O_CNT + smi[O_DST + k]], 1);
    __syncthreads();

    // ---------------- Phase 2: es/ed dots + prefix sum
    {
        int n = tid >> 3, h = tid & 7;
        const ulonglong2* hr = (const ulonglong2*)&sm[O_H1 + (n*8 + h)*RS];
        const ulonglong2* as = (const ulonglong2*)(aS1 + h*HID);
        const ulonglong2* ad = (const ulonglong2*)(aD1 + h*HID);
        u64t e0 = 0ull, e1 = 0ull, d0 = 0ull, d1 = 0ull;
        #pragma unroll
        for (int kk = 0; kk < 16; kk++) {
            ulonglong2 v = hr[kk], a = as[kk], g = ad[kk];
            fma2(e0, v.x, a.x);
            fma2(e1, v.y, a.y);
            fma2(d0, v.x, g.x);
            fma2(d1, v.y, g.y);
        }
        sm[O_ES + n*8 + h] = red2(e0, e1);
        sm[O_ED + n*8 + h] = red2(d0, d1);
    }
    if (tid == 0) {
        int acc = 0;
        for (int d = 0; d < NN; d++) { smi[O_OFF + d] = acc; acc += smi[O_CNT + d]; }
        smi[O_OFF + NN] = acc;
    }
    __syncthreads();

    // ---------------- Phase 3: edge scores + CSR scatter
    for (int k = tid; k < ET; k += NTH) {
        int s = smi[O_SRC + k], d = smi[O_DST + k];
        const float4* es = (const float4*)&sm[O_ES + s*8];
        const float4* ed = (const float4*)&sm[O_ED + d*8];
        float4* eo = (float4*)&sm[O_E + k*8];
        float4 a0 = es[0], a1 = es[1], b0 = ed[0], b1 = ed[1];
        float4 r0, r1;
        r0.x = lreluf_(a0.x + b0.x); r0.y = lreluf_(a0.y + b0.y);
        r0.z = lreluf_(a0.z + b0.z); r0.w = lreluf_(a0.w + b0.w);
        r1.x = lreluf_(a1.x + b1.x); r1.y = lreluf_(a1.y + b1.y);
        r1.z = lreluf_(a1.z + b1.z); r1.w = lreluf_(a1.w + b1.w);
        eo[0] = r0; eo[1] = r1;
    }
    for (int k = tid; k < ET; k += NTH)
        smi[O_CSR + smi[O_OFF + smi[O_DST + k]] + smi[O_SLOT + k]] = k;
    __syncthreads();

    // ---------------- Phase 4: GAT1 softmax + aggregation
    {
        int dst = tid >> 3, h = tid & 7;
        int o   = smi[O_OFF + dst], deg = smi[O_OFF + dst + 1] - o;
        float m = -1e30f;
        for (int i = 0; i < deg; i++)
            m = fmaxf(m, sm[O_E + smi[O_CSR + o + i]*8 + h]);
        float s = 0.f;
        for (int i = 0; i < deg; i++) {
            int k = smi[O_CSR + o + i];
            float p = __expf(sm[O_E + k*8 + h] - m);
            sm[O_E + k*8 + h] = p;
            s += p;
        }
        float inv = __fdividef(1.f, s + 1e-16f);
        u64t acc[32];
        #pragma unroll
        for (int j = 0; j < 32; j++) acc[j] = 0ull;
        for (int i = 0; i < deg; i++) {
            int k = smi[O_CSR + o + i];
            u64t pp = pk2(sm[O_E + k*8 + h], sm[O_E + k*8 + h]);
            const ulonglong2* hr = (const ulonglong2*)&sm[O_H1 + (smi[O_SRC + k]*8 + h)*RS];
            #pragma unroll
            for (int j = 0; j < 16; j++) {
                ulonglong2 v = hr[j];
                fma2(acc[2*j],   pp, v.x);
                fma2(acc[2*j+1], pp, v.y);
            }
        }
        __syncthreads();
        float4* orow = (float4*)&sm[O_H1 + (dst*8 + h)*RS];
        const float4* bb = (const float4*)(b1 + h*HID);
        #pragma unroll
        for (int j = 0; j < 16; j++) {
            float4 bv = bb[j], r;
            float2 lo = up2(acc[2*j]), hi = up2(acc[2*j+1]);
            r.x = eluf_(fmaf(lo.x, inv, bv.x));
            r.y = eluf_(fmaf(lo.y, inv, bv.y));
            r.z = eluf_(fmaf(hi.x, inv, bv.z));
            r.w = eluf_(fmaf(hi.y, inv, bv.w));
            orow[j] = r;
        }
    }
    __syncthreads();

    // ---------------- Phase 5: h2 = out1 @ W2 — 2 cols x 4 nodes per thread
    {
        int half = tid & 31;          // columns 2*half, 2*half+1
        int grp  = tid >> 5;          // nodes grp*4 .. grp*4+3
        u64t a0A[4], a0B[4], a1A[4], a1B[4];
        #pragma unroll
        for (int i = 0; i < 4; i++) { a0A[i]=0ull; a0B[i]=0ull; a1A[i]=0ull; a1B[i]=0ull; }
        for (int hd = 0; hd < 8; hd++) {
            const ulonglong2* w2p = ((const ulonglong2*)g_w2p) + hd*32*32 + half;
            #pragma unroll 4
            for (int kc = 0; kc < 64; kc += 4) {
                int p = kc >> 1;
                ulonglong2 wA = w2p[p*32];         // pair p:  (col0, col1)
                ulonglong2 wB = w2p[(p+1)*32];     // pair p+1
                #pragma unroll
                for (int i = 0; i < 4; i++) {
                    ulonglong2 v = *(const ulonglong2*)&sm[O_H1 + ((grp*4+i)*8 + hd)*RS + kc];
                    fma2(a0A[i], v.x, wA.x);
                    fma2(a1A[i], v.x, wA.y);
                    fma2(a0B[i], v.y, wB.x);
                    fma2(a1B[i], v.y, wB.y);
                }
            }
        }
        #pragma unroll
        for (int i = 0; i < 4; i++) {
            float2 o;
            o.x = red2(a0A[i], a0B[i]);
            o.y = red2(a1A[i], a1B[i]);
            *(float2*)&sm[O_H2 + (grp*4+i)*H2S + 2*half] = o;
        }
    }
    __syncthreads();

    // ---------------- Phase 6: GAT2 attention
    if (tid < 64) {
        int n = tid & 31;
        const ulonglong2* a  = (const ulonglong2*)((tid < 32) ? aS2 : aD2);
        const ulonglong2* hr = (const ulonglong2*)&sm[O_H2 + n*H2S];
        u64t a0 = 0ull, a1 = 0ull;
        #pragma unroll
        for (int kk = 0; kk < 16; kk++) {
            ulonglong2 v = hr[kk], w = a[kk];
            fma2(a0, v.x, w.x);
            fma2(a1, v.y, w.y);
        }
        sm[(tid < 32 ? O_ES2 : O_ED2) + n] = red2(a0, a1);
    }
    __syncthreads();
    for (int k = tid; k < ET; k += NTH)
        sm[O_E2 + k] = lreluf_(sm[O_ES2 + smi[O_SRC + k]] + sm[O_ED2 + smi[O_DST + k]]);
    __syncthreads();
    if (tid < NN) {
        int o = smi[O_OFF + tid], deg = smi[O_OFF + tid + 1] - o;
        float m = -1e30f;
        for (int i = 0; i < deg; i++) m = fmaxf(m, sm[O_E2 + smi[O_CSR + o + i]]);
        float s = 0.f;
        for (int i = 0; i < deg; i++) s += __expf(sm[O_E2 + smi[O_CSR + o + i]] - m);
        sm[O_M2 + tid]  = m;
        sm[O_IS2 + tid] = __fdividef(1.f, s + 1e-16f);
    }
    __syncthreads();
    for (int k = tid; k < ET; k += NTH) {
        int d = smi[O_DST + k];
        sm[O_AL2 + k] = __expf(sm[O_E2 + k] - sm[O_M2 + d]) * sm[O_IS2 + d];
    }
    __syncthreads();
    {
        int dst = tid >> 3, cc = (tid & 7) * 8;
        int o = smi[O_OFF + dst], deg = smi[O_OFF + dst + 1] - o;
        u64t a0 = 0ull, a1 = 0ull, a2 = 0ull, a3 = 0ull;
        for (int i = 0; i < deg; i++) {
            int k = smi[O_CSR + o + i];
            float al = sm[O_AL2 + k];
            u64t pp = pk2(al, al);
            const ulonglong2* hr = (const ulonglong2*)&sm[O_H2 + smi[O_SRC + k]*H2S + cc];
            ulonglong2 v0 = hr[0], v1 = hr[1];
            fma2(a0, pp, v0.x);
            fma2(a1, pp, v0.y);
            fma2(a2, pp, v1.x);
            fma2(a3, pp, v1.y);
        }
        const float4* bb = (const float4*)(b2 + cc);
        float4 b0 = bb[0], b1v = bb[1], r0, r1;
        float2 f0 = up2(a0), f1 = up2(a1), f2 = up2(a2), f3 = up2(a3);
        r0.x = eluf_(f0.x + b0.x); r0.y = eluf_(f0.y + b0.y);
        r0.z = eluf_(f1.x + b0.z); r0.w = eluf_(f1.y + b0.w);
        r1.x = eluf_(f2.x + b1v.x); r1.y = eluf_(f2.y + b1v.y);
        r1.z = eluf_(f3.x + b1v.z); r1.w = eluf_(f3.y + b1v.w);
        float4* g = (float4*)&sm[O_G2 + dst*H2S + cc];
        g[0] = r0; g[1] = r1;
    }
    __syncthreads();

    // ---------------- Phase 7: LayerNorm + transpose -> hlnT[t][n]
    if (tid < NN) {
        const float4* r4 = (const float4*)&sm[O_G2 + tid*H2S];
        float4 row[16];
        float mu = 0.f;
        #pragma unroll
        for (int kk = 0; kk < 16; kk++) {
            row[kk] = r4[kk];
            mu += (row[kk].x + row[kk].y) + (row[kk].z + row[kk].w);
        }
        mu *= (1.f/HID);
        float var = 0.f;
        #pragma unroll
        for (int kk = 0; kk < 16; kk++) {
            float dx = row[kk].x-mu, dy = row[kk].y-mu, dz = row[kk].z-mu, dw = row[kk].w-mu;
            var += fmaf(dx,dx, dy*dy) + fmaf(dz,dz, dw*dw);
        }
        var *= (1.f/HID);
        float is = rsqrtf(var + 1e-5f);
        #pragma unroll
        for (int kk = 0; kk < 16; kk++) {
            int t = kk*4;
            sm[O_HLNT + (t+0)*HLNTS + tid] = (row[kk].x - mu)*is*gamma[t+0] + beta[t+0];
            sm[O_HLNT + (t+1)*HLNTS + tid] = (row[kk].y - mu)*is*gamma[t+1] + beta[t+1];
            sm[O_HLNT + (t+2)*HLNTS + tid] = (row[kk].z - mu)*is*gamma[t+2] + beta[t+2];
            sm[O_HLNT + (t+3)*HLNTS + tid] = (row[kk].w - mu)*is*gamma[t+3] + beta[t+3];
        }
    }
    __syncthreads();

    const int wrp  = tid >> 5;
    const int lane = tid & 31;

    // ---------------- Phase 8: xi1 = hlnT @ Wi1^T + bi1 (all 8 warps, 24 tiles)
    for (int tile = wrp; tile < 24; tile += 8) {
        int j0 = (tile >> 1) * 16;
        int t  = (tile & 1) * 32 + lane;
        xi_tile32(Wi1, bi1, &sm[O_HLNT + t*HLNTS], &sm[O_XI + t*XIS + j0], j0);
    }
    // Wh1 rows into registers (threads 0..191)
    u64t wh2[32]; float bh = 0.f;
    if (tid < 192) {
        bh = bh1[tid];
        const ulonglong2* w = (const ulonglong2*)(Wh1 + tid*HID);
        #pragma unroll
        for (int kk = 0; kk < 16; kk++) {
            ulonglong2 t = w[kk];
            wh2[2*kk]   = t.x;
            wh2[2*kk+1] = t.y;
        }
    }
    if (tid < HID) sm[O_HSM + tid] = 0.f;
    __syncthreads();

    // ---------------- Phase 9: GRU1 recurrence (warps 0-5 only; warps 6-7 park)
    if (tid < 192) {
        for (int t = 0; t < HID; t++) {
            const ulonglong2* h4 = (const ulonglong2*)&sm[O_HSM];
            u64t a0 = 0ull, a1 = 0ull, a2 = 0ull, a3 = 0ull;
            #pragma unroll
            for (int kk = 0; kk < 8; kk++) {
                ulonglong2 v0 = h4[2*kk], v1 = h4[2*kk+1];
                fma2(a0, wh2[4*kk],   v0.x);
                fma2(a1, wh2[4*kk+1], v0.y);
                fma2(a2, wh2[4*kk+2], v1.x);
                fma2(a3, wh2[4*kk+3], v1.y);
            }
            sm[O_GH + tid] = bh + red4(a0, a1, a2, a3);
            BAR_SYNC(1, 192);
            if (tid < HID) {
                const float* xr = &sm[O_XI + t*XIS];
                float r  = sigmf_(xr[tid]       + sm[O_GH + tid]);
                float z  = sigmf_(xr[64 + tid]  + sm[O_GH + 64 + tid]);
                float nv = tanhf_(fmaf(r, sm[O_GH + 128 + tid], xr[128 + tid]));
                float hn = (1.f - z)*nv + z*sm[O_HSM + tid];
                sm[O_HSM + tid]        = hn;
                sm[O_YS + t*YSS + tid] = hn;
            }
            BAR_SYNC(2, 192);
        }
    }
    __syncthreads();

    // ---------------- Phase 10: xi2 = ys @ Wi2^T + bi2 (all 8 warps)
    for (int tile = wrp; tile < 24; tile += 8) {
        int j0 = (tile >> 1) * 16;
        int t  = (tile & 1) * 32 + lane;
        xi_tile64(Wi2, bi2, &sm[O_YS + t*YSS], &sm[O_XI + t*XIS + j0], j0);
    }
    if (tid < 192) {
        bh = bh2[tid];
        const ulonglong2* w = (const ulonglong2*)(Wh2 + tid*HID);
        #pragma unroll
        for (int kk = 0; kk < 16; kk++) {
            ulonglong2 t = w[kk];
            wh2[2*kk]   = t.x;
            wh2[2*kk+1] = t.y;
        }
    }
    if (tid < HID) sm[O_HSM + tid] = 0.f;
    __syncthreads();

    // ---------------- Phase 11: GRU2 recurrence (warps 0-5 only)
    if (tid < 192) {
        for (int t = 0; t < HID; t++) {
            const ulonglong2* h4 = (const ulonglong2*)&sm[O_HSM];
            u64t a0 = 0ull, a1 = 0ull, a2 = 0ull, a3 = 0ull;
            #pragma unroll
            for (int kk = 0; kk < 8; kk++) {
                ulonglong2 v0 = h4[2*kk], v1 = h4[2*kk+1];
                fma2(a0, wh2[4*kk],   v0.x);
                fma2(a1, wh2[4*kk+1], v0.y);
                fma2(a2, wh2[4*kk+2], v1.x);
                fma2(a3, wh2[4*kk+3], v1.y);
            }
            sm[O_GH + tid] = bh + red4(a0, a1, a2, a3);
            BAR_SYNC(1, 192);
            if (tid < HID) {
                const float* xr = &sm[O_XI + t*XIS];
                float r  = sigmf_(xr[tid]       + sm[O_GH + tid]);
                float z  = sigmf_(xr[64 + tid]  + sm[O_GH + 64 + tid]);
                float nv = tanhf_(fmaf(r, sm[O_GH + 128 + tid], xr[128 + tid]));
                sm[O_HSM + tid] = (1.f - z)*nv + z*sm[O_HSM + tid];
            }
            BAR_SYNC(2, 192);
        }
    }
    __syncthreads();

    // ---------------- Phase 12: final linear
    if (tid < 9) {
        const ulonglong2* w = (const ulonglong2*)(Wf + tid*HID);
        const ulonglong2* h4 = (const ulonglong2*)&sm[O_HSM];
        u64t a0 = 0ull, a1 = 0ull;
        #pragma unroll
        for (int kk = 0; kk < 16; kk++) {
            ulonglong2 wv = w[kk], hv = h4[kk];
            fma2(a0, wv.x, hv.x);
            fma2(a1, wv.y, hv.y);
        }
        out[b*9 + tid] = bf[tid] + red2(a0, a1);
    }
}

extern "C" void kernel_launch(void* const* d_in, const int* in_sizes, int n_in,
                              void* d_out, int out_size) {
    (void)in_sizes; (void)n_in; (void)out_size;
    const float* x    = (const float*)d_in[0];
    const int*   ei   = (const int*)  d_in[1];
    const float* W1   = (const float*)d_in[2];
    const float* aS1  = (const float*)d_in[3];
    const float* aD1  = (const float*)d_in[4];
    const float* b1   = (const float*)d_in[5];
    const float* W2   = (const float*)d_in[6];
    const float* aS2  = (const float*)d_in[7];
    const float* aD2  = (const float*)d_in[8];
    const float* b2   = (const float*)d_in[9];
    const float* gam  = (const float*)d_in[10];
    const float* bet  = (const float*)d_in[11];
    const float* Wi1  = (const float*)d_in[12];
    const float* Wh1  = (const float*)d_in[13];
    const float* bi1  = (const float*)d_in[14];
    const float* bh1  = (const float*)d_in[15];
    const float* Wi2  = (const float*)d_in[16];
    const float* Wh2  = (const float*)d_in[17];
    const float* bi2  = (const float*)d_in[18];
    const float* bh2  = (const float*)d_in[19];
    const float* Wf   = (const float*)d_in[20];
    const float* bf   = (const float*)d_in[21];
    float* out = (float*)d_out;

    size_t smem = (size_t)SMEM_FLOATS * sizeof(float);
    cudaFuncSetAttribute(fused_gatgru_kernel,
                         cudaFuncAttributeMaxDynamicSharedMemorySize, (int)smem);
    pack_weights_kernel<<<64, 256>>>(W1, W2);
    fused_gatgru_kernel<<<512, NTH, smem>>>(
        x, ei, W1, aS1, aD1, b1, W2, aS2, aD2, b2, gam, bet,
        Wi1, Wh1, bi1, bh1, Wi2, Wh2, bi2, bh2, Wf, bf, out);
}